// round 1
// baseline (speedup 1.0000x reference)
#include <cuda_runtime.h>
#include <math.h>

#define HH 96
#define WW 96
#define HW 9216
#define BATCH 4

// ---------------- scratch (static device globals; no allocation) ----------------
__device__ float g_h0[BATCH * 64 * HW];
__device__ float g_h1[BATCH * 64 * HW];
__device__ float g_off[BATCH * 288 * HW];
__device__ float g_mask[BATCH * 144 * HW];
__device__ float g_xt[BATCH * HW * 128];   // NHWC transpose of x
__device__ float g_wd[1152 * 64];          // deform weight, [kk][o] with kk = g*72 + k*8 + c

// ---------------- transpose x: NCHW -> N(HW)C ----------------
__global__ void transpose_x_kernel(const float* __restrict__ x, float* __restrict__ xt) {
    __shared__ float t[32][33];
    int b = blockIdx.z, y = blockIdx.y;
    int c0 = (blockIdx.x & 3) * 32;
    int w0 = (blockIdx.x >> 2) * 32;
    int tx = threadIdx.x, ty = threadIdx.y;
#pragma unroll
    for (int j = 0; j < 4; j++) {
        int c = c0 + ty + j * 8;
        t[ty + j * 8][tx] = x[((b * 128 + c) * HH + y) * WW + w0 + tx];
    }
    __syncthreads();
#pragma unroll
    for (int j = 0; j < 4; j++) {
        int w = w0 + ty + j * 8;
        xt[((size_t)b * HW + (size_t)y * WW + w) * 128 + c0 + tx] = t[tx][ty + j * 8];
    }
}

// ---------------- deform-weight transpose: weight[o][g*8+c][k] -> wd[(g*72+k*8+c)][o] ----------------
__global__ void prep_wd_kernel(const float* __restrict__ wgt, float* __restrict__ wd) {
    int i = blockIdx.x * 256 + threadIdx.x;   // < 73728
    int kk = i >> 6, o = i & 63;
    int g = kk / 72, r = kk - g * 72;
    int k = r >> 3, c = r & 7;
    wd[i] = wgt[(o * 128 + g * 8 + c) * 9 + k];
}

// ---------------- generic 3x3 SAME conv ----------------
// MODE 0: concat input (extra_feat|flow1|flow2), lrelu epilogue, Cout=64
// MODE 1: plain input, lrelu epilogue, Cout=64
// MODE 2: plain input, offset/mask epilogue (tanh/sigmoid/flow add), Cout=432
template <int CIN, int MODE>
__global__ void conv3x3_kernel(
    const float* __restrict__ in,
    const float* __restrict__ extra,
    const float* __restrict__ flow1,
    const float* __restrict__ flow2,
    const float* __restrict__ wgt,
    const float* __restrict__ bias,
    float* __restrict__ out,
    float* __restrict__ out2)
{
    __shared__ float s_in[4][34][34];
    __shared__ float s_w[4][4][9];

    int b = blockIdx.z;
    int oc0 = blockIdx.y * 4;
    int tile = blockIdx.x;
    int gy0 = (tile / 3) * 32, gx0 = (tile - (tile / 3) * 3) * 32;
    int tx = threadIdx.x, ty = threadIdx.y;
    int tid = ty * 32 + tx;

    float acc[4][4];
#pragma unroll
    for (int o = 0; o < 4; o++)
#pragma unroll
        for (int r = 0; r < 4; r++) acc[o][r] = 0.f;

    for (int c0 = 0; c0 < CIN; c0 += 4) {
        // ---- stage input tile (with halo, zero-padded) ----
        for (int i = tid; i < 4 * 34 * 34; i += 256) {
            int ck = i / 1156;
            int rem = i - ck * 1156;
            int yy = rem / 34, xx = rem - yy * 34;
            int gy = gy0 + yy - 1, gx = gx0 + xx - 1;
            float v = 0.f;
            if ((unsigned)gy < HH && (unsigned)gx < WW) {
                int c = c0 + ck;
                if (MODE == 0) {
                    if (c < 192)       v = extra[((b * 192 + c) * HH + gy) * WW + gx];
                    else if (c < 194)  v = flow1[((b * 2 + (c - 192)) * HH + gy) * WW + gx];
                    else               v = flow2[((b * 2 + (c - 194)) * HH + gy) * WW + gx];
                } else {
                    v = in[((b * CIN + c) * HH + gy) * WW + gx];
                }
            }
            s_in[ck][yy][xx] = v;
        }
        // ---- stage weights ----
        if (tid < 144) {
            int o = tid / 36, rem = tid - o * 36;
            int ck = rem / 9, k = rem - ck * 9;
            s_w[o][ck][k] = wgt[((oc0 + o) * CIN + c0 + ck) * 9 + k];
        }
        __syncthreads();

        // ---- compute: this thread = column tx, rows ty*4..ty*4+3, 4 out channels ----
#pragma unroll
        for (int ck = 0; ck < 4; ck++) {
            float v[6][3];
#pragma unroll
            for (int r = 0; r < 6; r++)
#pragma unroll
                for (int cc = 0; cc < 3; cc++)
                    v[r][cc] = s_in[ck][ty * 4 + r][tx + cc];
#pragma unroll
            for (int o = 0; o < 4; o++) {
#pragma unroll
                for (int ky = 0; ky < 3; ky++)
#pragma unroll
                    for (int kx = 0; kx < 3; kx++) {
                        float wv = s_w[o][ck][ky * 3 + kx];
#pragma unroll
                        for (int rr = 0; rr < 4; rr++)
                            acc[o][rr] += wv * v[rr + ky][kx];
                    }
            }
        }
        __syncthreads();
    }

    // ---- epilogue ----
#pragma unroll
    for (int o = 0; o < 4; o++) {
        int oc = oc0 + o;
        float bv = bias[oc];
#pragma unroll
        for (int rr = 0; rr < 4; rr++) {
            int gy = gy0 + ty * 4 + rr;
            int gx = gx0 + tx;
            float val = acc[o][rr] + bv;
            if (MODE <= 1) {
                val = (val >= 0.f) ? val : 0.1f * val;
                out[((b * 64 + oc) * HH + gy) * WW + gx] = val;
            } else {
                if (oc < 288) {
                    const float* fl = (oc < 144) ? flow1 : flow2;
                    float f = fl[((b * 2 + (1 - (oc & 1))) * HH + gy) * WW + gx];
                    out[((size_t)b * 288 * HW) + (size_t)oc * HW + gy * WW + gx] =
                        10.f * tanhf(val) + f;
                } else {
                    out2[((size_t)b * 144 * HW) + (size_t)(oc - 288) * HW + gy * WW + gx] =
                        1.f / (1.f + expf(-val));
                }
            }
        }
    }
}

// ---------------- deformable conv ----------------
// block = 256 threads, handles (b, h, w0..w0+15).
// phase 1: compute s[px][kk] samples into smem (kk = g*72 + k*8 + c), stride 1156 (bank-friendly)
// phase 2: out[16px][64oc] = s @ wd  (+bias)
#define SSTRIDE 1156

__global__ void deform_kernel(
    const float* __restrict__ xt,
    const float* __restrict__ off,
    const float* __restrict__ msk,
    const float* __restrict__ wd,
    const float* __restrict__ bias,
    float* __restrict__ out)
{
    extern __shared__ float s_sm[];   // 16 * SSTRIDE floats
    int b = blockIdx.z;
    int h = blockIdx.y;
    int w0 = blockIdx.x * 16;
    int tid = threadIdx.x;

    // ---------- phase 1 ----------
    {
        int px = tid & 15;
        int ww = w0 + px;
        int pospix = h * WW + ww;
        const float* offb = off + (size_t)b * 288 * HW + pospix;
        const float* mskb = msk + (size_t)b * 144 * HW + pospix;
        const float* xb = xt + (size_t)b * HW * 128;
#pragma unroll 1
        for (int it = 0; it < 9; it++) {
            int gk = (tid >> 4) + it * 16;          // 0..143
            int g = gk / 9, k = gk - g * 9;
            int ky = k / 3, kx = k - ky * 3;
            int oc = g * 18 + k * 2;
            float dy = offb[(size_t)oc * HW];
            float dx = offb[(size_t)(oc + 1) * HW];
            float m = mskb[(size_t)gk * HW];
            float py = dy + (float)(ky + h - 1);
            float pxx = dx + (float)(kx + ww - 1);
            float fy0 = floorf(py), fx0 = floorf(pxx);
            float wy1 = py - fy0, wx1 = pxx - fx0;
            int iy0 = (int)fy0, ix0 = (int)fx0;
            float a[8];
#pragma unroll
            for (int i = 0; i < 8; i++) a[i] = 0.f;
#pragma unroll
            for (int dyc = 0; dyc < 2; dyc++) {
#pragma unroll
                for (int dxc = 0; dxc < 2; dxc++) {
                    int yy = iy0 + dyc, xx = ix0 + dxc;
                    if ((unsigned)yy < HH && (unsigned)xx < WW) {
                        float wc = (dyc ? wy1 : 1.f - wy1) * (dxc ? wx1 : 1.f - wx1);
                        const float4* p = (const float4*)(xb + ((size_t)yy * WW + xx) * 128 + g * 8);
                        float4 v0 = p[0], v1 = p[1];
                        a[0] += wc * v0.x; a[1] += wc * v0.y; a[2] += wc * v0.z; a[3] += wc * v0.w;
                        a[4] += wc * v1.x; a[5] += wc * v1.y; a[6] += wc * v1.z; a[7] += wc * v1.w;
                    }
                }
            }
            float* sp = s_sm + px * SSTRIDE + g * 72 + k * 8;
            ((float4*)sp)[0] = make_float4(a[0] * m, a[1] * m, a[2] * m, a[3] * m);
            ((float4*)sp)[1] = make_float4(a[4] * m, a[5] * m, a[6] * m, a[7] * m);
        }
    }
    __syncthreads();

    // ---------- phase 2 ----------
    {
        int og = tid & 15;       // 4 output channels: og*4..og*4+3
        int p2 = tid >> 4;       // pixel 0..15
        const float4* wd4 = (const float4*)wd;
        const float* sr = s_sm + p2 * SSTRIDE;
        float4 bb = ((const float4*)bias)[og];
        float a0 = bb.x, a1 = bb.y, a2 = bb.z, a3 = bb.w;
#pragma unroll 8
        for (int kk = 0; kk < 1152; kk++) {
            float4 wv = wd4[kk * 16 + og];
            float sv = sr[kk];
            a0 += wv.x * sv;
            a1 += wv.y * sv;
            a2 += wv.z * sv;
            a3 += wv.w * sv;
        }
        int oc = og * 4;
        size_t ob = (size_t)b * 64 * HW + (size_t)h * WW + w0 + p2;
        out[ob + (size_t)(oc + 0) * HW] = a0;
        out[ob + (size_t)(oc + 1) * HW] = a1;
        out[ob + (size_t)(oc + 2) * HW] = a2;
        out[ob + (size_t)(oc + 3) * HW] = a3;
    }
}

// ---------------- launch ----------------
extern "C" void kernel_launch(void* const* d_in, const int* in_sizes, int n_in,
                              void* d_out, int out_size)
{
    const float* x      = (const float*)d_in[0];
    const float* extra  = (const float*)d_in[1];
    const float* flow1  = (const float*)d_in[2];
    const float* flow2  = (const float*)d_in[3];
    const float* weight = (const float*)d_in[4];
    const float* bias   = (const float*)d_in[5];
    const float* ow0    = (const float*)d_in[6];
    const float* ob0    = (const float*)d_in[7];
    const float* ow1    = (const float*)d_in[8];
    const float* ob1    = (const float*)d_in[9];
    const float* ow2    = (const float*)d_in[10];
    const float* ob2    = (const float*)d_in[11];
    const float* ow3    = (const float*)d_in[12];
    const float* ob3    = (const float*)d_in[13];
    float* out = (float*)d_out;

    void *ph0, *ph1, *poff, *pmask, *pxt, *pwd;
    cudaGetSymbolAddress(&ph0, g_h0);
    cudaGetSymbolAddress(&ph1, g_h1);
    cudaGetSymbolAddress(&poff, g_off);
    cudaGetSymbolAddress(&pmask, g_mask);
    cudaGetSymbolAddress(&pxt, g_xt);
    cudaGetSymbolAddress(&pwd, g_wd);
    float* h0 = (float*)ph0;
    float* h1 = (float*)ph1;
    float* offb = (float*)poff;
    float* maskb = (float*)pmask;
    float* xtb = (float*)pxt;
    float* wdb = (float*)pwd;

    dim3 tb(32, 8);

    // transpose x -> NHWC
    transpose_x_kernel<<<dim3(12, 96, BATCH), tb>>>(x, xtb);
    // weight transpose for deform GEMM
    prep_wd_kernel<<<288, 256>>>(weight, wdb);

    // conv chain
    conv3x3_kernel<196, 0><<<dim3(9, 16, BATCH), tb>>>(
        nullptr, extra, flow1, flow2, ow0, ob0, h0, nullptr);
    conv3x3_kernel<64, 1><<<dim3(9, 16, BATCH), tb>>>(
        h0, nullptr, nullptr, nullptr, ow1, ob1, h1, nullptr);
    conv3x3_kernel<64, 1><<<dim3(9, 16, BATCH), tb>>>(
        h1, nullptr, nullptr, nullptr, ow2, ob2, h0, nullptr);
    conv3x3_kernel<64, 2><<<dim3(9, 108, BATCH), tb>>>(
        h0, nullptr, flow1, flow2, ow3, ob3, offb, maskb);

    // deformable conv
    int smem = 16 * SSTRIDE * (int)sizeof(float);   // 73984 bytes
    cudaFuncSetAttribute(deform_kernel, cudaFuncAttributeMaxDynamicSharedMemorySize, smem);
    deform_kernel<<<dim3(6, 96, BATCH), 256, smem>>>(xtb, offb, maskb, wdb, bias, out);
}

// round 3
// speedup vs baseline: 1.0937x; 1.0937x over previous
#include <cuda_runtime.h>
#include <math.h>

#define HH 96
#define WW 96
#define HW 9216
#define BATCH 4

typedef unsigned long long ull;

// ---------------- scratch (static device globals; no allocation) ----------------
__device__ float g_h0[BATCH * 64 * HW];
__device__ float g_h1[BATCH * 64 * HW];
__device__ float g_off[BATCH * 288 * HW];
__device__ float g_mask[BATCH * 144 * HW];
__device__ float g_xt[BATCH * HW * 128];   // NHWC transpose of x
__device__ float g_wd[1152 * 64];          // deform weight, [kk][o] with kk = g*72 + k*8 + c

// ---------------- packed f32x2 helpers ----------------
__device__ __forceinline__ void fma2(ull& d, ull a, ull b) {
    asm("fma.rn.f32x2 %0, %1, %2, %0;" : "+l"(d) : "l"(a), "l"(b));
}
__device__ __forceinline__ ull pack2(float lo, float hi) {
    ull r;
    asm("mov.b64 %0, {%1, %2};" : "=l"(r) : "f"(lo), "f"(hi));
    return r;
}
__device__ __forceinline__ void unpack2(ull p, float& lo, float& hi) {
    asm("mov.b64 {%0, %1}, %2;" : "=f"(lo), "=f"(hi) : "l"(p));
}
__device__ __forceinline__ ull midpair(ull a, ull b) {
    // {hi(a), lo(b)}
    return (a >> 32) | (b << 32);
}

// ---------------- transpose x: NCHW -> N(HW)C ----------------
__global__ void transpose_x_kernel(const float* __restrict__ x, float* __restrict__ xt) {
    __shared__ float t[32][33];
    int b = blockIdx.z, y = blockIdx.y;
    int c0 = (blockIdx.x & 3) * 32;
    int w0 = (blockIdx.x >> 2) * 32;
    int tx = threadIdx.x, ty = threadIdx.y;
#pragma unroll
    for (int j = 0; j < 4; j++) {
        int c = c0 + ty + j * 8;
        t[ty + j * 8][tx] = x[((b * 128 + c) * HH + y) * WW + w0 + tx];
    }
    __syncthreads();
#pragma unroll
    for (int j = 0; j < 4; j++) {
        int w = w0 + ty + j * 8;
        xt[((size_t)b * HW + (size_t)y * WW + w) * 128 + c0 + tx] = t[tx][ty + j * 8];
    }
}

// ---------------- deform-weight transpose ----------------
__global__ void prep_wd_kernel(const float* __restrict__ wgt, float* __restrict__ wd) {
    int i = blockIdx.x * 256 + threadIdx.x;   // < 73728
    int kk = i >> 6, o = i & 63;
    int g = kk / 72, r = kk - g * 72;
    int k = r >> 3, c = r & 7;
    wd[i] = wgt[(o * 128 + g * 8 + c) * 9 + k];
}

// ---------------- generic 3x3 SAME conv, f32x2 packed ----------------
// Tile: 32 cols x 48 rows. Block (16,12)=192 threads.
// Thread: 2 adjacent cols (2*tx), 4 rows (ty*4..+3), 4 out channels.
// MODE 0: concat input, lrelu.  MODE 1: plain, lrelu.  MODE 2: offset/mask epilogue.
template <int CIN, int MODE>
__global__ __launch_bounds__(192, 3) void conv3x3_kernel(
    const float* __restrict__ in,
    const float* __restrict__ extra,
    const float* __restrict__ flow1,
    const float* __restrict__ flow2,
    const float* __restrict__ wgt,
    const float* __restrict__ bias,
    float* __restrict__ out,
    float* __restrict__ out2)
{
    __shared__ float s_in[4][50][34];
    __shared__ float2 s_w2[4][4][9];   // [o][ck][k] = {w,w}

    int b = blockIdx.z;
    int oc0 = blockIdx.y * 4;
    int tile = blockIdx.x;                 // 0..5
    int gx0 = (tile % 3) * 32;
    int gy0 = (tile / 3) * 48;
    int tx = threadIdx.x;                  // 0..15
    int ty = threadIdx.y;                  // 0..11
    int tid = ty * 16 + tx;

    // staging assignment: thread -> one (ck, xx) column (tid < 136)
    int sck = tid / 34;
    int sxx = tid - sck * 34;
    int sgx = gx0 + sxx - 1;
    bool sactive = (tid < 136);
    bool xok = sactive && ((unsigned)sgx < WW);

    ull acc[4][4];
#pragma unroll
    for (int o = 0; o < 4; o++)
#pragma unroll
        for (int r = 0; r < 4; r++) acc[o][r] = 0ULL;

    for (int c0 = 0; c0 < CIN; c0 += 4) {
        // ---- stage input: column walk, no div/mod in loop ----
        if (sactive) {
            const float* src = nullptr;
            if (MODE == 0) {
                int c = c0 + sck;
                if (c < 192)      src = extra + ((size_t)(b * 192 + c)) * HW;
                else if (c < 194) src = flow1 + ((size_t)(b * 2 + (c - 192))) * HW;
                else              src = flow2 + ((size_t)(b * 2 + (c - 194))) * HW;
            } else {
                src = in + ((size_t)(b * CIN + c0 + sck)) * HW;
            }
#pragma unroll 5
            for (int yy = 0; yy < 50; yy++) {
                int gy = gy0 + yy - 1;
                float v = 0.f;
                if (xok && (unsigned)gy < HH) v = src[gy * WW + sgx];
                s_in[sck][yy][sxx] = v;
            }
        }
        // ---- stage weights (duplicated pairs) ----
        if (tid < 144) {
            int o = tid / 36, rem = tid - o * 36;
            int ck = rem / 9, k = rem - ck * 9;
            float w = wgt[((oc0 + o) * CIN + c0 + ck) * 9 + k];
            s_w2[o][ck][k] = make_float2(w, w);
        }
        __syncthreads();

        // ---- compute ----
#pragma unroll
        for (int ck = 0; ck < 4; ck++) {
            // load v pairs: 6 halo rows, 3 col-pairs each
            ull P[6][3];
#pragma unroll
            for (int iy = 0; iy < 6; iy++) {
                const float* rp = &s_in[ck][ty * 4 + iy][2 * tx];
                ull a = *(const ull*)rp;          // cols (2tx, 2tx+1)
                ull c = *(const ull*)(rp + 2);    // cols (2tx+2, 2tx+3)
                P[iy][0] = a;
                P[iy][2] = c;
                P[iy][1] = midpair(a, c);         // cols (2tx+1, 2tx+2)
            }
#pragma unroll
            for (int o = 0; o < 4; o++) {
                const float2* wrow = s_w2[o][ck];
#pragma unroll
                for (int ky = 0; ky < 3; ky++) {
#pragma unroll
                    for (int kx = 0; kx < 3; kx++) {
                        ull w2 = *(const ull*)&wrow[ky * 3 + kx];  // broadcast LDS.64
#pragma unroll
                        for (int r = 0; r < 4; r++)
                            fma2(acc[o][r], P[r + ky][kx], w2);
                    }
                }
            }
        }
        __syncthreads();
    }

    // ---- epilogue ----
#pragma unroll
    for (int o = 0; o < 4; o++) {
        int oc = oc0 + o;
        float bv = bias[oc];
#pragma unroll
        for (int rr = 0; rr < 4; rr++) {
            int gy = gy0 + ty * 4 + rr;
            int gx = gx0 + 2 * tx;
            float v0, v1;
            unpack2(acc[o][rr], v0, v1);
            v0 += bv; v1 += bv;
            if (MODE <= 1) {
                v0 = (v0 >= 0.f) ? v0 : 0.1f * v0;
                v1 = (v1 >= 0.f) ? v1 : 0.1f * v1;
                *(float2*)&out[((b * 64 + oc) * HH + gy) * WW + gx] = make_float2(v0, v1);
            } else {
                if (oc < 288) {
                    const float* fl = (oc < 144) ? flow1 : flow2;
                    const float* fr = fl + ((size_t)(b * 2 + (1 - (oc & 1)))) * HW + gy * WW + gx;
                    float2 f = *(const float2*)fr;
                    float2 r = make_float2(10.f * tanhf(v0) + f.x, 10.f * tanhf(v1) + f.y);
                    *(float2*)&out[(size_t)b * 288 * HW + (size_t)oc * HW + gy * WW + gx] = r;
                } else {
                    float2 r = make_float2(1.f / (1.f + expf(-v0)), 1.f / (1.f + expf(-v1)));
                    *(float2*)&out2[(size_t)b * 144 * HW + (size_t)(oc - 288) * HW + gy * WW + gx] = r;
                }
            }
        }
    }
}

// ---------------- deformable conv ----------------
#define SSTRIDE 1156

__global__ void deform_kernel(
    const float* __restrict__ xt,
    const float* __restrict__ off,
    const float* __restrict__ msk,
    const float* __restrict__ wd,
    const float* __restrict__ bias,
    float* __restrict__ out)
{
    extern __shared__ float s_sm[];   // 16 * SSTRIDE floats
    int b = blockIdx.z;
    int h = blockIdx.y;
    int w0 = blockIdx.x * 16;
    int tid = threadIdx.x;

    // ---------- phase 1: bilinear gather into smem ----------
    {
        int px = tid & 15;
        int ww = w0 + px;
        int pospix = h * WW + ww;
        const float* offb = off + (size_t)b * 288 * HW + pospix;
        const float* mskb = msk + (size_t)b * 144 * HW + pospix;
        const float* xb = xt + (size_t)b * HW * 128;
#pragma unroll 1
        for (int it = 0; it < 9; it++) {
            int gk = (tid >> 4) + it * 16;          // 0..143
            int g = gk / 9, k = gk - g * 9;
            int ky = k / 3, kx = k - ky * 3;
            int oc = g * 18 + k * 2;
            float dy = offb[(size_t)oc * HW];
            float dx = offb[(size_t)(oc + 1) * HW];
            float m = mskb[(size_t)gk * HW];
            float py = dy + (float)(ky + h - 1);
            float pxx = dx + (float)(kx + ww - 1);
            float fy0 = floorf(py), fx0 = floorf(pxx);
            float wy1 = py - fy0, wx1 = pxx - fx0;
            int iy0 = (int)fy0, ix0 = (int)fx0;
            float a[8];
#pragma unroll
            for (int i = 0; i < 8; i++) a[i] = 0.f;
#pragma unroll
            for (int dyc = 0; dyc < 2; dyc++) {
#pragma unroll
                for (int dxc = 0; dxc < 2; dxc++) {
                    int yy = iy0 + dyc, xx = ix0 + dxc;
                    if ((unsigned)yy < HH && (unsigned)xx < WW) {
                        float wc = (dyc ? wy1 : 1.f - wy1) * (dxc ? wx1 : 1.f - wx1);
                        const float4* p = (const float4*)(xb + ((size_t)yy * WW + xx) * 128 + g * 8);
                        float4 v0 = p[0], v1 = p[1];
                        a[0] += wc * v0.x; a[1] += wc * v0.y; a[2] += wc * v0.z; a[3] += wc * v0.w;
                        a[4] += wc * v1.x; a[5] += wc * v1.y; a[6] += wc * v1.z; a[7] += wc * v1.w;
                    }
                }
            }
            float* sp = s_sm + px * SSTRIDE + g * 72 + k * 8;
            ((float4*)sp)[0] = make_float4(a[0] * m, a[1] * m, a[2] * m, a[3] * m);
            ((float4*)sp)[1] = make_float4(a[4] * m, a[5] * m, a[6] * m, a[7] * m);
        }
    }
    __syncthreads();

    // ---------- phase 2: out[16px][64oc] = s @ wd, f32x2 packed ----------
    {
        int og = tid & 15;       // 4 output channels: og*4..og*4+3
        int p2 = tid >> 4;       // pixel 0..15
        const ulonglong2* wdv = (const ulonglong2*)wd;
        const float4* sr4 = (const float4*)(s_sm + p2 * SSTRIDE);
        float4 bb = ((const float4*)bias)[og];
        ull a01 = pack2(bb.x, bb.y);
        ull a23 = pack2(bb.z, bb.w);
#pragma unroll 2
        for (int kk4 = 0; kk4 < 288; kk4++) {
            float4 sv = sr4[kk4];
            {
                ull ss = pack2(sv.x, sv.x);
                ulonglong2 wv = wdv[(kk4 * 4 + 0) * 16 + og];
                fma2(a01, wv.x, ss); fma2(a23, wv.y, ss);
            }
            {
                ull ss = pack2(sv.y, sv.y);
                ulonglong2 wv = wdv[(kk4 * 4 + 1) * 16 + og];
                fma2(a01, wv.x, ss); fma2(a23, wv.y, ss);
            }
            {
                ull ss = pack2(sv.z, sv.z);
                ulonglong2 wv = wdv[(kk4 * 4 + 2) * 16 + og];
                fma2(a01, wv.x, ss); fma2(a23, wv.y, ss);
            }
            {
                ull ss = pack2(sv.w, sv.w);
                ulonglong2 wv = wdv[(kk4 * 4 + 3) * 16 + og];
                fma2(a01, wv.x, ss); fma2(a23, wv.y, ss);
            }
        }
        float r0, r1, r2, r3;
        unpack2(a01, r0, r1);
        unpack2(a23, r2, r3);
        int oc = og * 4;
        size_t ob = (size_t)b * 64 * HW + (size_t)h * WW + w0 + p2;
        out[ob + (size_t)(oc + 0) * HW] = r0;
        out[ob + (size_t)(oc + 1) * HW] = r1;
        out[ob + (size_t)(oc + 2) * HW] = r2;
        out[ob + (size_t)(oc + 3) * HW] = r3;
    }
}

// ---------------- launch ----------------
extern "C" void kernel_launch(void* const* d_in, const int* in_sizes, int n_in,
                              void* d_out, int out_size)
{
    const float* x      = (const float*)d_in[0];
    const float* extra  = (const float*)d_in[1];
    const float* flow1  = (const float*)d_in[2];
    const float* flow2  = (const float*)d_in[3];
    const float* weight = (const float*)d_in[4];
    const float* bias   = (const float*)d_in[5];
    const float* ow0    = (const float*)d_in[6];
    const float* ob0    = (const float*)d_in[7];
    const float* ow1    = (const float*)d_in[8];
    const float* ob1    = (const float*)d_in[9];
    const float* ow2    = (const float*)d_in[10];
    const float* ob2    = (const float*)d_in[11];
    const float* ow3    = (const float*)d_in[12];
    const float* ob3    = (const float*)d_in[13];
    float* out = (float*)d_out;

    void *ph0, *ph1, *poff, *pmask, *pxt, *pwd;
    cudaGetSymbolAddress(&ph0, g_h0);
    cudaGetSymbolAddress(&ph1, g_h1);
    cudaGetSymbolAddress(&poff, g_off);
    cudaGetSymbolAddress(&pmask, g_mask);
    cudaGetSymbolAddress(&pxt, g_xt);
    cudaGetSymbolAddress(&pwd, g_wd);
    float* h0 = (float*)ph0;
    float* h1 = (float*)ph1;
    float* offb = (float*)poff;
    float* maskb = (float*)pmask;
    float* xtb = (float*)pxt;
    float* wdb = (float*)pwd;

    // transpose x -> NHWC
    transpose_x_kernel<<<dim3(12, 96, BATCH), dim3(32, 8)>>>(x, xtb);
    // weight transpose for deform GEMM
    prep_wd_kernel<<<288, 256>>>(weight, wdb);

    dim3 cb(16, 12);
    // conv chain
    conv3x3_kernel<196, 0><<<dim3(6, 16, BATCH), cb>>>(
        nullptr, extra, flow1, flow2, ow0, ob0, h0, nullptr);
    conv3x3_kernel<64, 1><<<dim3(6, 16, BATCH), cb>>>(
        h0, nullptr, nullptr, nullptr, ow1, ob1, h1, nullptr);
    conv3x3_kernel<64, 1><<<dim3(6, 16, BATCH), cb>>>(
        h1, nullptr, nullptr, nullptr, ow2, ob2, h0, nullptr);
    conv3x3_kernel<64, 2><<<dim3(6, 108, BATCH), cb>>>(
        h0, nullptr, flow1, flow2, ow3, ob3, offb, maskb);

    // deformable conv
    int smem = 16 * SSTRIDE * (int)sizeof(float);   // 73984 bytes
    cudaFuncSetAttribute(deform_kernel, cudaFuncAttributeMaxDynamicSharedMemorySize, smem);
    deform_kernel<<<dim3(6, 96, BATCH), 256, smem>>>(xtb, offb, maskb, wdb, bias, out);
}

// round 6
// speedup vs baseline: 1.2162x; 1.1121x over previous
#include <cuda_runtime.h>
#include <math.h>

#define HH 96
#define WW 96
#define HW 9216
#define BATCH 4

typedef unsigned long long ull;

// ---------------- scratch (static device globals; no allocation) ----------------
__device__ float g_h0[BATCH * 64 * HW];
__device__ float g_h1[BATCH * 64 * HW];
__device__ float g_off[BATCH * 288 * HW];
__device__ float g_mask[BATCH * 144 * HW];
__device__ float g_xt[BATCH * HW * 128];   // NHWC transpose of x
__device__ float g_wd[1152 * 64];          // deform weight, [kk][o] with kk = g*72 + k*8 + c

// ---------------- packed f32x2 helpers ----------------
__device__ __forceinline__ void fma2(ull& d, ull a, ull b) {
    asm("fma.rn.f32x2 %0, %1, %2, %0;" : "+l"(d) : "l"(a), "l"(b));
}
__device__ __forceinline__ ull pack2(float lo, float hi) {
    ull r;
    asm("mov.b64 %0, {%1, %2};" : "=l"(r) : "f"(lo), "f"(hi));
    return r;
}
__device__ __forceinline__ void unpack2(ull p, float& lo, float& hi) {
    asm("mov.b64 {%0, %1}, %2;" : "=f"(lo), "=f"(hi) : "l"(p));
}
__device__ __forceinline__ ull midpair(ull a, ull b) {
    // {hi(a), lo(b)}
    return (a >> 32) | (b << 32);
}

// ---------------- transpose x: NCHW -> N(HW)C ----------------
__global__ void transpose_x_kernel(const float* __restrict__ x, float* __restrict__ xt) {
    __shared__ float t[32][33];
    int b = blockIdx.z, y = blockIdx.y;
    int c0 = (blockIdx.x & 3) * 32;
    int w0 = (blockIdx.x >> 2) * 32;
    int tx = threadIdx.x, ty = threadIdx.y;
#pragma unroll
    for (int j = 0; j < 4; j++) {
        int c = c0 + ty + j * 8;
        t[ty + j * 8][tx] = x[((b * 128 + c) * HH + y) * WW + w0 + tx];
    }
    __syncthreads();
#pragma unroll
    for (int j = 0; j < 4; j++) {
        int w = w0 + ty + j * 8;
        xt[((size_t)b * HW + (size_t)y * WW + w) * 128 + c0 + tx] = t[tx][ty + j * 8];
    }
}

// ---------------- deform-weight transpose ----------------
__global__ void prep_wd_kernel(const float* __restrict__ wgt, float* __restrict__ wd) {
    int i = blockIdx.x * 256 + threadIdx.x;   // < 73728
    int kk = i >> 6, o = i & 63;
    int g = kk / 72, r = kk - g * 72;
    int k = r >> 3, c = r & 7;
    wd[i] = wgt[(o * 128 + g * 8 + c) * 9 + k];
}

// ---------------- 3x3 SAME conv, full-width tiles, f32x2 ----------------
// Tile: 96 cols x 8 rows. Block = 96 threads (tx 0..47 => col pair, ty 0..1 => 4 rows).
// Thread: 2 cols (2*tx, 2*tx+1), 4 rows, 4 out channels => 16 f32x2 accumulators.
// smem j = global_col + 1; j=0 and j=97..99 are permanent zeros (halo/pad).
// MODE 0: concat input, lrelu.  MODE 1: plain, lrelu.  MODE 2: offset/mask epilogue.
#define SROW 100
template <int CIN, int MODE>
__global__ __launch_bounds__(96) void conv3x3_kernel(
    const float* __restrict__ in,
    const float* __restrict__ extra,
    const float* __restrict__ flow1,
    const float* __restrict__ flow2,
    const float* __restrict__ wgt,
    const float* __restrict__ bias,
    float* __restrict__ out,
    float* __restrict__ out2)
{
    __shared__ float s_in[4][10][SROW];
    __shared__ float2 s_w2[4][4][9];   // [o][ck][k] = {w,w}

    int b = blockIdx.z;
    int oc0 = blockIdx.y * 4;
    int gy0 = blockIdx.x * 8;              // 12 tiles of 8 rows
    int tid = threadIdx.x;                 // 0..95
    int tx = tid % 48;
    int ty = tid / 48;                     // 0..1

    // staging mapping: q = float4 col group (global cols 4q..4q+3), rl = row lane
    int q = tid % 24;
    int rl = tid / 24;                     // 0..3

    // permanent zero halo columns (written once, never overwritten)
    if (tid < 40) {
        int ck = tid / 10, r = tid - ck * 10;
        s_in[ck][r][0] = 0.f;
        s_in[ck][r][97] = 0.f;
        s_in[ck][r][98] = 0.f;
        s_in[ck][r][99] = 0.f;
    }

    ull acc[4][4];
#pragma unroll
    for (int o = 0; o < 4; o++)
#pragma unroll
        for (int r = 0; r < 4; r++) acc[o][r] = 0ULL;

    __syncthreads();

    for (int c0 = 0; c0 < CIN; c0 += 4) {
        // ---- stage input: rows gy0-1 .. gy0+8, coalesced float4 loads ----
#pragma unroll
        for (int i = 0; i < 3; i++) {
            int rr = rl + 4 * i;
            if (rr < 10) {
                int gy = gy0 + rr - 1;
                bool vy = (unsigned)gy < (unsigned)HH;
#pragma unroll
                for (int ck = 0; ck < 4; ck++) {
                    const float* src;
                    if (MODE == 0) {
                        int c = c0 + ck;
                        if (c < 192)      src = extra + ((size_t)(b * 192 + c)) * HW;
                        else if (c < 194) src = flow1 + ((size_t)(b * 2 + (c - 192))) * HW;
                        else              src = flow2 + ((size_t)(b * 2 + (c - 194))) * HW;
                    } else {
                        src = in + ((size_t)(b * CIN + c0 + ck)) * HW;
                    }
                    float4 v = make_float4(0.f, 0.f, 0.f, 0.f);
                    if (vy) v = *(const float4*)(src + gy * WW + 4 * q);
                    float* d = &s_in[ck][rr][1 + 4 * q];
                    d[0] = v.x; d[1] = v.y; d[2] = v.z; d[3] = v.w;
                }
            }
        }
        // ---- stage weights (duplicated pairs) ----
#pragma unroll
        for (int wi = 0; wi < 2; wi++) {
            int widx = tid + wi * 96;
            if (widx < 144) {
                int o = widx / 36, rem = widx - o * 36;
                int ck = rem / 9, k = rem - ck * 9;
                float w = wgt[((oc0 + o) * CIN + c0 + ck) * 9 + k];
                s_w2[o][ck][k] = make_float2(w, w);
            }
        }
        __syncthreads();

        // ---- compute ----
#pragma unroll
        for (int ck = 0; ck < 4; ck++) {
            ull P[6][3];
#pragma unroll
            for (int iy = 0; iy < 6; iy++) {
                const float* rp = &s_in[ck][ty * 4 + iy][2 * tx];
                ull a = *(const ull*)rp;          // j = 2tx,2tx+1  (kx=0 pair)
                ull c = *(const ull*)(rp + 2);    // j = 2tx+2,2tx+3 (kx=2 pair)
                P[iy][0] = a;
                P[iy][1] = midpair(a, c);         // kx=1 pair
                P[iy][2] = c;
            }
#pragma unroll
            for (int o = 0; o < 4; o++) {
                const float2* wrow = s_w2[o][ck];
#pragma unroll
                for (int ky = 0; ky < 3; ky++) {
#pragma unroll
                    for (int kx = 0; kx < 3; kx++) {
                        ull w2 = *(const ull*)&wrow[ky * 3 + kx];
#pragma unroll
                        for (int r = 0; r < 4; r++)
                            fma2(acc[o][r], P[r + ky][kx], w2);
                    }
                }
            }
        }
        __syncthreads();
    }

    // ---- epilogue ----
#pragma unroll
    for (int o = 0; o < 4; o++) {
        int oc = oc0 + o;
        float bv = bias[oc];
#pragma unroll
        for (int rr = 0; rr < 4; rr++) {
            int gy = gy0 + ty * 4 + rr;
            int gx = 2 * tx;
            float v0, v1;
            unpack2(acc[o][rr], v0, v1);
            v0 += bv; v1 += bv;
            if (MODE <= 1) {
                v0 = (v0 >= 0.f) ? v0 : 0.1f * v0;
                v1 = (v1 >= 0.f) ? v1 : 0.1f * v1;
                *(float2*)&out[((b * 64 + oc) * HH + gy) * WW + gx] = make_float2(v0, v1);
            } else {
                if (oc < 288) {
                    const float* fl = (oc < 144) ? flow1 : flow2;
                    const float* fr = fl + ((size_t)(b * 2 + (1 - (oc & 1)))) * HW + gy * WW + gx;
                    float2 f = *(const float2*)fr;
                    float2 r = make_float2(10.f * tanhf(v0) + f.x, 10.f * tanhf(v1) + f.y);
                    *(float2*)&out[(size_t)b * 288 * HW + (size_t)oc * HW + gy * WW + gx] = r;
                } else {
                    float2 r = make_float2(1.f / (1.f + expf(-v0)), 1.f / (1.f + expf(-v1)));
                    *(float2*)&out2[(size_t)b * 144 * HW + (size_t)(oc - 288) * HW + gy * WW + gx] = r;
                }
            }
        }
    }
}

// ---------------- deformable conv ----------------
#define SSTRIDE 1156

__global__ void deform_kernel(
    const float* __restrict__ xt,
    const float* __restrict__ off,
    const float* __restrict__ msk,
    const float* __restrict__ wd,
    const float* __restrict__ bias,
    float* __restrict__ out)
{
    extern __shared__ float s_sm[];   // 16 * SSTRIDE floats
    int b = blockIdx.z;
    int h = blockIdx.y;
    int w0 = blockIdx.x * 16;
    int tid = threadIdx.x;

    // ---------- phase 1: bilinear gather into smem ----------
    {
        int px = tid & 15;
        int ww = w0 + px;
        int pospix = h * WW + ww;
        const float* offb = off + (size_t)b * 288 * HW + pospix;
        const float* mskb = msk + (size_t)b * 144 * HW + pospix;
        const float* xb = xt + (size_t)b * HW * 128;
#pragma unroll 1
        for (int it = 0; it < 9; it++) {
            int gk = (tid >> 4) + it * 16;          // 0..143
            int g = gk / 9, k = gk - g * 9;
            int ky = k / 3, kx = k - ky * 3;
            int oc = g * 18 + k * 2;
            float dy = offb[(size_t)oc * HW];
            float dx = offb[(size_t)(oc + 1) * HW];
            float m = mskb[(size_t)gk * HW];
            float py = dy + (float)(ky + h - 1);
            float pxx = dx + (float)(kx + ww - 1);
            float fy0 = floorf(py), fx0 = floorf(pxx);
            float wy1 = py - fy0, wx1 = pxx - fx0;
            int iy0 = (int)fy0, ix0 = (int)fx0;
            float a[8];
#pragma unroll
            for (int i = 0; i < 8; i++) a[i] = 0.f;
#pragma unroll
            for (int dyc = 0; dyc < 2; dyc++) {
#pragma unroll
                for (int dxc = 0; dxc < 2; dxc++) {
                    int yy = iy0 + dyc, xx = ix0 + dxc;
                    if ((unsigned)yy < HH && (unsigned)xx < WW) {
                        float wc = (dyc ? wy1 : 1.f - wy1) * (dxc ? wx1 : 1.f - wx1);
                        const float4* p = (const float4*)(xb + ((size_t)yy * WW + xx) * 128 + g * 8);
                        float4 v0 = p[0], v1 = p[1];
                        a[0] += wc * v0.x; a[1] += wc * v0.y; a[2] += wc * v0.z; a[3] += wc * v0.w;
                        a[4] += wc * v1.x; a[5] += wc * v1.y; a[6] += wc * v1.z; a[7] += wc * v1.w;
                    }
                }
            }
            float* sp = s_sm + px * SSTRIDE + g * 72 + k * 8;
            ((float4*)sp)[0] = make_float4(a[0] * m, a[1] * m, a[2] * m, a[3] * m);
            ((float4*)sp)[1] = make_float4(a[4] * m, a[5] * m, a[6] * m, a[7] * m);
        }
    }
    __syncthreads();

    // ---------- phase 2: out[16px][64oc] = s @ wd, f32x2 packed ----------
    {
        int og = tid & 15;       // 4 output channels: og*4..og*4+3
        int p2 = tid >> 4;       // pixel 0..15
        const ulonglong2* wdv = (const ulonglong2*)wd;
        const float4* sr4 = (const float4*)(s_sm + p2 * SSTRIDE);
        float4 bb = ((const float4*)bias)[og];
        ull a01 = pack2(bb.x, bb.y);
        ull a23 = pack2(bb.z, bb.w);
#pragma unroll 2
        for (int kk4 = 0; kk4 < 288; kk4++) {
            float4 sv = sr4[kk4];
            {
                ull ss = pack2(sv.x, sv.x);
                ulonglong2 wv = wdv[(kk4 * 4 + 0) * 16 + og];
                fma2(a01, wv.x, ss); fma2(a23, wv.y, ss);
            }
            {
                ull ss = pack2(sv.y, sv.y);
                ulonglong2 wv = wdv[(kk4 * 4 + 1) * 16 + og];
                fma2(a01, wv.x, ss); fma2(a23, wv.y, ss);
            }
            {
                ull ss = pack2(sv.z, sv.z);
                ulonglong2 wv = wdv[(kk4 * 4 + 2) * 16 + og];
                fma2(a01, wv.x, ss); fma2(a23, wv.y, ss);
            }
            {
                ull ss = pack2(sv.w, sv.w);
                ulonglong2 wv = wdv[(kk4 * 4 + 3) * 16 + og];
                fma2(a01, wv.x, ss); fma2(a23, wv.y, ss);
            }
        }
        float r0, r1, r2, r3;
        unpack2(a01, r0, r1);
        unpack2(a23, r2, r3);
        int oc = og * 4;
        size_t ob = (size_t)b * 64 * HW + (size_t)h * WW + w0 + p2;
        out[ob + (size_t)(oc + 0) * HW] = r0;
        out[ob + (size_t)(oc + 1) * HW] = r1;
        out[ob + (size_t)(oc + 2) * HW] = r2;
        out[ob + (size_t)(oc + 3) * HW] = r3;
    }
}

// ---------------- launch ----------------
extern "C" void kernel_launch(void* const* d_in, const int* in_sizes, int n_in,
                              void* d_out, int out_size)
{
    const float* x      = (const float*)d_in[0];
    const float* extra  = (const float*)d_in[1];
    const float* flow1  = (const float*)d_in[2];
    const float* flow2  = (const float*)d_in[3];
    const float* weight = (const float*)d_in[4];
    const float* bias   = (const float*)d_in[5];
    const float* ow0    = (const float*)d_in[6];
    const float* ob0    = (const float*)d_in[7];
    const float* ow1    = (const float*)d_in[8];
    const float* ob1    = (const float*)d_in[9];
    const float* ow2    = (const float*)d_in[10];
    const float* ob2    = (const float*)d_in[11];
    const float* ow3    = (const float*)d_in[12];
    const float* ob3    = (const float*)d_in[13];
    float* out = (float*)d_out;

    void *ph0, *ph1, *poff, *pmask, *pxt, *pwd;
    cudaGetSymbolAddress(&ph0, g_h0);
    cudaGetSymbolAddress(&ph1, g_h1);
    cudaGetSymbolAddress(&poff, g_off);
    cudaGetSymbolAddress(&pmask, g_mask);
    cudaGetSymbolAddress(&pxt, g_xt);
    cudaGetSymbolAddress(&pwd, g_wd);
    float* h0 = (float*)ph0;
    float* h1 = (float*)ph1;
    float* offb = (float*)poff;
    float* maskb = (float*)pmask;
    float* xtb = (float*)pxt;
    float* wdb = (float*)pwd;

    // transpose x -> NHWC
    transpose_x_kernel<<<dim3(12, 96, BATCH), dim3(32, 8)>>>(x, xtb);
    // weight transpose for deform GEMM
    prep_wd_kernel<<<288, 256>>>(weight, wdb);

    // conv chain (96-thread blocks, 12 spatial tiles)
    conv3x3_kernel<196, 0><<<dim3(12, 16, BATCH), 96>>>(
        nullptr, extra, flow1, flow2, ow0, ob0, h0, nullptr);
    conv3x3_kernel<64, 1><<<dim3(12, 16, BATCH), 96>>>(
        h0, nullptr, nullptr, nullptr, ow1, ob1, h1, nullptr);
    conv3x3_kernel<64, 1><<<dim3(12, 16, BATCH), 96>>>(
        h1, nullptr, nullptr, nullptr, ow2, ob2, h0, nullptr);
    conv3x3_kernel<64, 2><<<dim3(12, 108, BATCH), 96>>>(
        h0, nullptr, flow1, flow2, ow3, ob3, offb, maskb);

    // deformable conv
    int smem = 16 * SSTRIDE * (int)sizeof(float);   // 73984 bytes
    cudaFuncSetAttribute(deform_kernel, cudaFuncAttributeMaxDynamicSharedMemorySize, smem);
    deform_kernel<<<dim3(6, 96, BATCH), 256, smem>>>(xtb, offb, maskb, wdb, bias, out);
}

// round 7
// speedup vs baseline: 1.2864x; 1.0577x over previous
#include <cuda_runtime.h>
#include <cuda_pipeline.h>
#include <math.h>

#define HH 96
#define WW 96
#define HW 9216
#define BATCH 4

typedef unsigned long long ull;

// ---------------- scratch (static device globals; no allocation) ----------------
__device__ float g_h0[BATCH * 64 * HW];
__device__ float g_h1[BATCH * 64 * HW];
__device__ float g_off[BATCH * 288 * HW];
__device__ float g_mask[BATCH * 144 * HW];
__device__ float g_xt[BATCH * HW * 128];   // NHWC transpose of x
__device__ float g_wd[1152 * 64];          // deform weight, [kk][o]

// ---------------- packed f32x2 helpers ----------------
__device__ __forceinline__ void fma2(ull& d, ull a, ull b) {
    asm("fma.rn.f32x2 %0, %1, %2, %0;" : "+l"(d) : "l"(a), "l"(b));
}
__device__ __forceinline__ ull pack2(float lo, float hi) {
    ull r;
    asm("mov.b64 %0, {%1, %2};" : "=l"(r) : "f"(lo), "f"(hi));
    return r;
}
__device__ __forceinline__ void unpack2(ull p, float& lo, float& hi) {
    asm("mov.b64 {%0, %1}, %2;" : "=f"(lo), "=f"(hi) : "l"(p));
}
__device__ __forceinline__ ull midpair(ull a, ull b) {
    return (a >> 32) | (b << 32);   // {hi(a), lo(b)}
}

// ---------------- transpose x: NCHW -> N(HW)C ----------------
__global__ void transpose_x_kernel(const float* __restrict__ x, float* __restrict__ xt) {
    __shared__ float t[32][33];
    int b = blockIdx.z, y = blockIdx.y;
    int c0 = (blockIdx.x & 3) * 32;
    int w0 = (blockIdx.x >> 2) * 32;
    int tx = threadIdx.x, ty = threadIdx.y;
#pragma unroll
    for (int j = 0; j < 4; j++) {
        int c = c0 + ty + j * 8;
        t[ty + j * 8][tx] = x[((b * 128 + c) * HH + y) * WW + w0 + tx];
    }
    __syncthreads();
#pragma unroll
    for (int j = 0; j < 4; j++) {
        int w = w0 + ty + j * 8;
        xt[((size_t)b * HW + (size_t)y * WW + w) * 128 + c0 + tx] = t[tx][ty + j * 8];
    }
}

// ---------------- deform-weight transpose ----------------
__global__ void prep_wd_kernel(const float* __restrict__ wgt, float* __restrict__ wd) {
    int i = blockIdx.x * 256 + threadIdx.x;   // < 73728
    int kk = i >> 6, o = i & 63;
    int g = kk / 72, r = kk - g * 72;
    int k = r >> 3, c = r & 7;
    wd[i] = wgt[(o * 128 + g * 8 + c) * 9 + k];
}

// ---------------- 3x3 SAME conv, pipelined cp.async staging, f32x2 ----------------
// Tile: 96 cols x 8 rows. Block = 96 threads. Thread: 2 cols, 4 rows, 4 oc.
// smem layout: interior col g at j = 4+g (16B-aligned async dst); j<4 and j>=100 zero halo.
#define SROW 104
template <int CIN, int MODE>
__device__ __forceinline__ const float* src_ptr(
    int b, int c, const float* in, const float* extra,
    const float* flow1, const float* flow2)
{
    if (MODE == 0) {
        if (c < 192)      return extra + (size_t)(b * 192 + c) * HW;
        else if (c < 194) return flow1 + (size_t)(b * 2 + (c - 192)) * HW;
        else              return flow2 + (size_t)(b * 2 + (c - 194)) * HW;
    }
    return in + (size_t)(b * CIN + c) * HW;
}

template <int CIN, int MODE>
__global__ __launch_bounds__(96) void conv3x3_kernel(
    const float* __restrict__ in,
    const float* __restrict__ extra,
    const float* __restrict__ flow1,
    const float* __restrict__ flow2,
    const float* __restrict__ wgt,
    const float* __restrict__ bias,
    float* __restrict__ out,
    float* __restrict__ out2)
{
    __shared__ float s_in[2][4][10][SROW];
    __shared__ float2 s_w2[144];   // [o*36 + ck*9 + k] = {w,w}

    const int b = blockIdx.z;
    const int oc0 = blockIdx.y * 4;
    const int gy0 = blockIdx.x * 8;        // 12 tiles of 8 rows
    const int tid = threadIdx.x;           // 0..95
    const int tx = tid % 48;
    const int ty = tid / 48;               // 0..1
    const int nsteps = CIN / 4;

    // ---- pre-zero halo columns (both buffers), once ----
    const float4 z4 = make_float4(0.f, 0.f, 0.f, 0.f);
    for (int i = tid; i < 160; i += 96) {
        int bi = i / 80, rem = i % 80;
        int ck = rem / 20, rem2 = rem % 20;
        int r = rem2 >> 1, side = rem2 & 1;
        *(float4*)&s_in[bi][ck][r][side ? 100 : 0] = z4;
    }
    // ---- pre-zero out-of-range rows (both buffers), once ----
    if (gy0 == 0 || gy0 == 88) {
        int rr = (gy0 == 0) ? 0 : 9;
        for (int i = tid; i < 208; i += 96) {
            int bi = i / 104, rem = i % 104;
            int ck = rem / 26, q = rem % 26;
            ((float4*)&s_in[bi][ck][rr][0])[q] = z4;
        }
    }

    // weight index decomposition for this thread (2 slots)
    const int t0 = tid, t1 = tid + 96;          // t1 < 144 only for tid < 48
    const int o_0 = t0 / 36, ck_0 = (t0 % 36) / 9, k_0 = t0 % 9;
    const int o_1 = t1 / 36, ck_1 = (t1 % 36) / 9, k_1 = t1 % 9;

    // ---- preload weights for step 0 into smem (duplicated) ----
    {
        float w = wgt[((oc0 + o_0) * CIN + ck_0) * 9 + k_0];
        s_w2[t0] = make_float2(w, w);
        if (t1 < 144) {
            float w2v = wgt[((oc0 + o_1) * CIN + ck_1) * 9 + k_1];
            s_w2[t1] = make_float2(w2v, w2v);
        }
    }

    // staging decomposition: 960 16B copies per step, 10 per thread
    // t = tid + 96*i ; q = t%24 (col group), rc = t/24, ck = rc/10, rr = rc%10
    // ---- stage step 0 ----
    {
        const int c0 = 0;
#pragma unroll
        for (int i = 0; i < 10; i++) {
            int t = tid + 96 * i;
            int q = t % 24, rc = t / 24;
            int ck = rc / 10, rr = rc - ck * 10;
            int gy = gy0 + rr - 1;
            if ((unsigned)gy < (unsigned)HH) {
                const float* src = src_ptr<CIN, MODE>(b, c0 + ck, in, extra, flow1, flow2);
                __pipeline_memcpy_async(&s_in[0][ck][rr][4 + 4 * q],
                                        src + gy * WW + 4 * q, 16);
            }
        }
        __pipeline_commit();
    }

    ull acc[4][4];
#pragma unroll
    for (int o = 0; o < 4; o++)
#pragma unroll
        for (int r = 0; r < 4; r++) acc[o][r] = 0ULL;

    for (int s = 0; s < nsteps; s++) {
        const int bi = s & 1;
        float wn0 = 0.f, wn1 = 0.f;
        if (s + 1 < nsteps) {
            const int c0n = (s + 1) * 4;
            // stage input for step s+1 into other buffer
#pragma unroll
            for (int i = 0; i < 10; i++) {
                int t = tid + 96 * i;
                int q = t % 24, rc = t / 24;
                int ck = rc / 10, rr = rc - ck * 10;
                int gy = gy0 + rr - 1;
                if ((unsigned)gy < (unsigned)HH) {
                    const float* src = src_ptr<CIN, MODE>(b, c0n + ck, in, extra, flow1, flow2);
                    __pipeline_memcpy_async(&s_in[bi ^ 1][ck][rr][4 + 4 * q],
                                            src + gy * WW + 4 * q, 16);
                }
            }
            __pipeline_commit();
            // weights for step s+1 -> registers (latency hidden by compute)
            wn0 = wgt[((oc0 + o_0) * CIN + c0n + ck_0) * 9 + k_0];
            if (t1 < 144) wn1 = wgt[((oc0 + o_1) * CIN + c0n + ck_1) * 9 + k_1];
            __pipeline_wait_prior(1);
        } else {
            __pipeline_wait_prior(0);
        }
        __syncthreads();   // buf[bi] + s_w2(step s) visible to all

        // ---- compute from buf[bi] ----
#pragma unroll
        for (int ck = 0; ck < 4; ck++) {
            ull P[6][3];
#pragma unroll
            for (int iy = 0; iy < 6; iy++) {
                const float* rp = &s_in[bi][ck][ty * 4 + iy][2 + 2 * tx];
                ull a = *(const ull*)rp;          // j = 2+2tx
                ull bb = *(const ull*)(rp + 2);   // j = 4+2tx
                ull c = *(const ull*)(rp + 4);    // j = 6+2tx
                P[iy][0] = midpair(a, bb);        // cols (gx-1, gx)
                P[iy][1] = bb;                    // cols (gx, gx+1)
                P[iy][2] = midpair(bb, c);        // cols (gx+1, gx+2)
            }
#pragma unroll
            for (int o = 0; o < 4; o++) {
                const float2* wrow = &s_w2[o * 36 + ck * 9];
#pragma unroll
                for (int ky = 0; ky < 3; ky++) {
#pragma unroll
                    for (int kx = 0; kx < 3; kx++) {
                        ull w2 = *(const ull*)&wrow[ky * 3 + kx];
#pragma unroll
                        for (int r = 0; r < 4; r++)
                            fma2(acc[o][r], P[r + ky][kx], w2);
                    }
                }
            }
        }
        __syncthreads();   // all reads of buf[bi] + s_w2 done

        if (s + 1 < nsteps) {
            s_w2[t0] = make_float2(wn0, wn0);
            if (t1 < 144) s_w2[t1] = make_float2(wn1, wn1);
        }
    }

    // ---- epilogue ----
#pragma unroll
    for (int o = 0; o < 4; o++) {
        int oc = oc0 + o;
        float bv = bias[oc];
#pragma unroll
        for (int rr = 0; rr < 4; rr++) {
            int gy = gy0 + ty * 4 + rr;
            int gx = 2 * tx;
            float v0, v1;
            unpack2(acc[o][rr], v0, v1);
            v0 += bv; v1 += bv;
            if (MODE <= 1) {
                v0 = (v0 >= 0.f) ? v0 : 0.1f * v0;
                v1 = (v1 >= 0.f) ? v1 : 0.1f * v1;
                *(float2*)&out[((b * 64 + oc) * HH + gy) * WW + gx] = make_float2(v0, v1);
            } else {
                if (oc < 288) {
                    const float* fl = (oc < 144) ? flow1 : flow2;
                    const float* fr = fl + ((size_t)(b * 2 + (1 - (oc & 1)))) * HW + gy * WW + gx;
                    float2 f = *(const float2*)fr;
                    float2 r = make_float2(10.f * tanhf(v0) + f.x, 10.f * tanhf(v1) + f.y);
                    *(float2*)&out[(size_t)b * 288 * HW + (size_t)oc * HW + gy * WW + gx] = r;
                } else {
                    float2 r = make_float2(1.f / (1.f + expf(-v0)), 1.f / (1.f + expf(-v1)));
                    *(float2*)&out2[(size_t)b * 144 * HW + (size_t)(oc - 288) * HW + gy * WW + gx] = r;
                }
            }
        }
    }
}

// ---------------- deformable conv ----------------
#define SSTRIDE 1156

__global__ void deform_kernel(
    const float* __restrict__ xt,
    const float* __restrict__ off,
    const float* __restrict__ msk,
    const float* __restrict__ wd,
    const float* __restrict__ bias,
    float* __restrict__ out)
{
    extern __shared__ float s_sm[];   // 16 * SSTRIDE floats
    int b = blockIdx.z;
    int h = blockIdx.y;
    int w0 = blockIdx.x * 16;
    int tid = threadIdx.x;

    // ---------- phase 1: bilinear gather into smem ----------
    {
        int px = tid & 15;
        int ww = w0 + px;
        int pospix = h * WW + ww;
        const float* offb = off + (size_t)b * 288 * HW + pospix;
        const float* mskb = msk + (size_t)b * 144 * HW + pospix;
        const float* xb = xt + (size_t)b * HW * 128;
#pragma unroll 1
        for (int it = 0; it < 9; it++) {
            int gk = (tid >> 4) + it * 16;          // 0..143
            int g = gk / 9, k = gk - g * 9;
            int ky = k / 3, kx = k - ky * 3;
            int oc = g * 18 + k * 2;
            float dy = offb[(size_t)oc * HW];
            float dx = offb[(size_t)(oc + 1) * HW];
            float m = mskb[(size_t)gk * HW];
            float py = dy + (float)(ky + h - 1);
            float pxx = dx + (float)(kx + ww - 1);
            float fy0 = floorf(py), fx0 = floorf(pxx);
            float wy1 = py - fy0, wx1 = pxx - fx0;
            int iy0 = (int)fy0, ix0 = (int)fx0;
            float a[8];
#pragma unroll
            for (int i = 0; i < 8; i++) a[i] = 0.f;
#pragma unroll
            for (int dyc = 0; dyc < 2; dyc++) {
#pragma unroll
                for (int dxc = 0; dxc < 2; dxc++) {
                    int yy = iy0 + dyc, xx = ix0 + dxc;
                    if ((unsigned)yy < HH && (unsigned)xx < WW) {
                        float wc = (dyc ? wy1 : 1.f - wy1) * (dxc ? wx1 : 1.f - wx1);
                        const float4* p = (const float4*)(xb + ((size_t)yy * WW + xx) * 128 + g * 8);
                        float4 v0 = p[0], v1 = p[1];
                        a[0] += wc * v0.x; a[1] += wc * v0.y; a[2] += wc * v0.z; a[3] += wc * v0.w;
                        a[4] += wc * v1.x; a[5] += wc * v1.y; a[6] += wc * v1.z; a[7] += wc * v1.w;
                    }
                }
            }
            float* sp = s_sm + px * SSTRIDE + g * 72 + k * 8;
            ((float4*)sp)[0] = make_float4(a[0] * m, a[1] * m, a[2] * m, a[3] * m);
            ((float4*)sp)[1] = make_float4(a[4] * m, a[5] * m, a[6] * m, a[7] * m);
        }
    }
    __syncthreads();

    // ---------- phase 2: out[16px][64oc] = s @ wd, f32x2 packed ----------
    {
        int og = tid & 15;       // 4 output channels: og*4..og*4+3
        int p2 = tid >> 4;       // pixel 0..15
        const ulonglong2* wdv = (const ulonglong2*)wd;
        const float4* sr4 = (const float4*)(s_sm + p2 * SSTRIDE);
        float4 bb = ((const float4*)bias)[og];
        ull a01 = pack2(bb.x, bb.y);
        ull a23 = pack2(bb.z, bb.w);
#pragma unroll 2
        for (int kk4 = 0; kk4 < 288; kk4++) {
            float4 sv = sr4[kk4];
            {
                ull ss = pack2(sv.x, sv.x);
                ulonglong2 wv = wdv[(kk4 * 4 + 0) * 16 + og];
                fma2(a01, wv.x, ss); fma2(a23, wv.y, ss);
            }
            {
                ull ss = pack2(sv.y, sv.y);
                ulonglong2 wv = wdv[(kk4 * 4 + 1) * 16 + og];
                fma2(a01, wv.x, ss); fma2(a23, wv.y, ss);
            }
            {
                ull ss = pack2(sv.z, sv.z);
                ulonglong2 wv = wdv[(kk4 * 4 + 2) * 16 + og];
                fma2(a01, wv.x, ss); fma2(a23, wv.y, ss);
            }
            {
                ull ss = pack2(sv.w, sv.w);
                ulonglong2 wv = wdv[(kk4 * 4 + 3) * 16 + og];
                fma2(a01, wv.x, ss); fma2(a23, wv.y, ss);
            }
        }
        float r0, r1, r2, r3;
        unpack2(a01, r0, r1);
        unpack2(a23, r2, r3);
        int oc = og * 4;
        size_t ob = (size_t)b * 64 * HW + (size_t)h * WW + w0 + p2;
        out[ob + (size_t)(oc + 0) * HW] = r0;
        out[ob + (size_t)(oc + 1) * HW] = r1;
        out[ob + (size_t)(oc + 2) * HW] = r2;
        out[ob + (size_t)(oc + 3) * HW] = r3;
    }
}

// ---------------- launch ----------------
extern "C" void kernel_launch(void* const* d_in, const int* in_sizes, int n_in,
                              void* d_out, int out_size)
{
    const float* x      = (const float*)d_in[0];
    const float* extra  = (const float*)d_in[1];
    const float* flow1  = (const float*)d_in[2];
    const float* flow2  = (const float*)d_in[3];
    const float* weight = (const float*)d_in[4];
    const float* bias   = (const float*)d_in[5];
    const float* ow0    = (const float*)d_in[6];
    const float* ob0    = (const float*)d_in[7];
    const float* ow1    = (const float*)d_in[8];
    const float* ob1    = (const float*)d_in[9];
    const float* ow2    = (const float*)d_in[10];
    const float* ob2    = (const float*)d_in[11];
    const float* ow3    = (const float*)d_in[12];
    const float* ob3    = (const float*)d_in[13];
    float* out = (float*)d_out;

    void *ph0, *ph1, *poff, *pmask, *pxt, *pwd;
    cudaGetSymbolAddress(&ph0, g_h0);
    cudaGetSymbolAddress(&ph1, g_h1);
    cudaGetSymbolAddress(&poff, g_off);
    cudaGetSymbolAddress(&pmask, g_mask);
    cudaGetSymbolAddress(&pxt, g_xt);
    cudaGetSymbolAddress(&pwd, g_wd);
    float* h0 = (float*)ph0;
    float* h1 = (float*)ph1;
    float* offb = (float*)poff;
    float* maskb = (float*)pmask;
    float* xtb = (float*)pxt;
    float* wdb = (float*)pwd;

    // transpose x -> NHWC
    transpose_x_kernel<<<dim3(12, 96, BATCH), dim3(32, 8)>>>(x, xtb);
    // weight transpose for deform GEMM
    prep_wd_kernel<<<288, 256>>>(weight, wdb);

    // conv chain (96-thread blocks, 12 spatial tiles, pipelined staging)
    conv3x3_kernel<196, 0><<<dim3(12, 16, BATCH), 96>>>(
        nullptr, extra, flow1, flow2, ow0, ob0, h0, nullptr);
    conv3x3_kernel<64, 1><<<dim3(12, 16, BATCH), 96>>>(
        h0, nullptr, nullptr, nullptr, ow1, ob1, h1, nullptr);
    conv3x3_kernel<64, 1><<<dim3(12, 16, BATCH), 96>>>(
        h1, nullptr, nullptr, nullptr, ow2, ob2, h0, nullptr);
    conv3x3_kernel<64, 2><<<dim3(12, 108, BATCH), 96>>>(
        h0, nullptr, flow1, flow2, ow3, ob3, offb, maskb);

    // deformable conv
    int smem = 16 * SSTRIDE * (int)sizeof(float);   // 73984 bytes
    cudaFuncSetAttribute(deform_kernel, cudaFuncAttributeMaxDynamicSharedMemorySize, smem);
    deform_kernel<<<dim3(6, 96, BATCH), 256, smem>>>(xtb, offb, maskb, wdb, bias, out);
}

// round 9
// speedup vs baseline: 1.3571x; 1.0550x over previous
#include <cuda_runtime.h>
#include <cuda_pipeline.h>
#include <math.h>

#define HH 96
#define WW 96
#define HW 9216
#define BATCH 4

typedef unsigned long long ull;

// ---------------- scratch (static device globals; no allocation) ----------------
__device__ float g_h0[BATCH * 64 * HW];
__device__ float g_h1[BATCH * 64 * HW];
__device__ float g_off[BATCH * 288 * HW];
__device__ float g_mask[BATCH * 144 * HW];
__device__ float g_xt[BATCH * HW * 128];   // NHWC transpose of x
__device__ float g_wd[1152 * 64];          // deform weight, [kk][o]

// ---------------- packed f32x2 helpers ----------------
__device__ __forceinline__ void fma2(ull& d, ull a, ull b) {
    asm("fma.rn.f32x2 %0, %1, %2, %0;" : "+l"(d) : "l"(a), "l"(b));
}
__device__ __forceinline__ ull pack2(float lo, float hi) {
    ull r;
    asm("mov.b64 %0, {%1, %2};" : "=l"(r) : "f"(lo), "f"(hi));
    return r;
}
__device__ __forceinline__ void unpack2(ull p, float& lo, float& hi) {
    asm("mov.b64 {%0, %1}, %2;" : "=f"(lo), "=f"(hi) : "l"(p));
}
__device__ __forceinline__ ull midpair(ull a, ull b) {
    return (a >> 32) | (b << 32);   // {hi(a), lo(b)}
}

// ---------------- transpose x: NCHW -> N(HW)C ----------------
__global__ void transpose_x_kernel(const float* __restrict__ x, float* __restrict__ xt) {
    __shared__ float t[32][33];
    int b = blockIdx.z, y = blockIdx.y;
    int c0 = (blockIdx.x & 3) * 32;
    int w0 = (blockIdx.x >> 2) * 32;
    int tx = threadIdx.x, ty = threadIdx.y;
#pragma unroll
    for (int j = 0; j < 4; j++) {
        int c = c0 + ty + j * 8;
        t[ty + j * 8][tx] = x[((b * 128 + c) * HH + y) * WW + w0 + tx];
    }
    __syncthreads();
#pragma unroll
    for (int j = 0; j < 4; j++) {
        int w = w0 + ty + j * 8;
        xt[((size_t)b * HW + (size_t)y * WW + w) * 128 + c0 + tx] = t[tx][ty + j * 8];
    }
}

// ---------------- deform-weight transpose ----------------
__global__ void prep_wd_kernel(const float* __restrict__ wgt, float* __restrict__ wd) {
    int i = blockIdx.x * 256 + threadIdx.x;   // < 73728
    int kk = i >> 6, o = i & 63;
    int g = kk / 72, r = kk - g * 72;
    int k = r >> 3, c = r & 7;
    wd[i] = wgt[(o * 128 + g * 8 + c) * 9 + k];
}

// ---------------- 3x3 SAME conv, 3-deep cp.async pipeline, 1 barrier/step ----------------
// Tile: 96 cols x 8 rows. Block = 96 threads. Thread: 2 cols, 4 rows, 4 oc.
// smem: interior col g at j = 4+g (16B-aligned cp.async dst); j<4 / j>=100 permanent zeros.
#define SROW 104
#define BUFELTS (4 * 10 * SROW)

template <int CIN, int MODE>
__global__ __launch_bounds__(96) void conv3x3_kernel(
    const float* __restrict__ in,
    const float* __restrict__ extra,
    const float* __restrict__ flow1,
    const float* __restrict__ flow2,
    const float* __restrict__ wgt,
    const float* __restrict__ bias,
    float* __restrict__ out,
    float* __restrict__ out2)
{
    __shared__ float s_in[3][4][10][SROW];
    __shared__ float2 s_w2[3][144];

    const int b = blockIdx.z;
    const int oc0 = blockIdx.y * 4;
    const int gy0 = blockIdx.x * 8;        // 12 tiles of 8 rows
    const int tid = threadIdx.x;           // 0..95
    const int tx = tid % 48;
    const int ty = tid / 48;               // 0..1
    const int nsteps = CIN / 4;

    // ---- pre-zero halo columns (all 3 buffers), once ----
    const float4 z4 = make_float4(0.f, 0.f, 0.f, 0.f);
    for (int i = tid; i < 240; i += 96) {
        int bi = i / 80, rem = i % 80;
        int ck = rem / 20, rem2 = rem % 20;
        int r = rem2 >> 1, side = rem2 & 1;
        *(float4*)&s_in[bi][ck][r][side ? 100 : 0] = z4;
    }
    // ---- pre-zero out-of-range rows (all 3 buffers), once ----
    if (gy0 == 0 || gy0 == 88) {
        int rr = (gy0 == 0) ? 0 : 9;
        for (int i = tid; i < 312; i += 96) {
            int bi = i / 104, rem = i % 104;
            int ck = rem / 26, q = rem % 26;
            ((float4*)&s_in[bi][ck][rr][0])[q] = z4;
        }
    }

    // ---- precompute staging offsets (10 x 16B copies per thread per step) ----
    int soff[10], doff[10];
    unsigned vmask = 0;
#pragma unroll
    for (int i = 0; i < 10; i++) {
        int t = tid + 96 * i;
        int q = t % 24, rc = t / 24;
        int ck = rc / 10, rr = rc - ck * 10;
        int gy = gy0 + rr - 1;
        soff[i] = ck * HW + gy * WW + 4 * q;
        doff[i] = rc * SROW + 4 + 4 * q;
        if ((unsigned)gy < (unsigned)HH) vmask |= 1u << i;
    }

    // weight slots for this thread
    const int t0 = tid, t1 = tid + 96;          // t1 < 144 only for tid < 48
    const int o_0 = t0 / 36, ck_0 = (t0 % 36) / 9, k_0 = t0 % 9;
    const int o_1 = t1 / 36, ck_1 = (t1 % 36) / 9, k_1 = t1 % 9;
    const int wi0 = ((oc0 + o_0) * CIN + ck_0) * 9 + k_0;
    const int wi1 = ((oc0 + o_1) * CIN + ck_1) * 9 + k_1;

    // staging helper (inlined twice)
#define STAGE_STEP(BI, C0)                                                                   \
    do {                                                                                     \
        float* db = &s_in[BI][0][0][0];                                                      \
        if (MODE != 0 || (C0) < 192) {                                                       \
            const float* base = (MODE == 0)                                                  \
                ? extra + (size_t)(b * 192 + (C0)) * HW                                      \
                : in + (size_t)(b * CIN + (C0)) * HW;                                        \
            _Pragma("unroll")                                                                \
            for (int i = 0; i < 10; i++)                                                     \
                if ((vmask >> i) & 1)                                                        \
                    __pipeline_memcpy_async(db + doff[i], base + soff[i], 16);               \
        } else {                                                                             \
            _Pragma("unroll")                                                                \
            for (int i = 0; i < 10; i++) {                                                   \
                if ((vmask >> i) & 1) {                                                      \
                    int t = tid + 96 * i;                                                    \
                    int q = t % 24, rc = t / 24;                                             \
                    int ck = rc / 10, rr = rc - ck * 10;                                     \
                    int gy = gy0 + rr - 1;                                                   \
                    const float* src = ((ck < 2) ? flow1 : flow2)                            \
                                       + (size_t)(b * 2 + (ck & 1)) * HW;                    \
                    __pipeline_memcpy_async(db + doff[i], src + gy * WW + 4 * q, 16);        \
                }                                                                            \
            }                                                                                \
        }                                                                                    \
    } while (0)

#define STAGE_W(BI, C0)                                                                      \
    do {                                                                                     \
        float w = wgt[wi0 + (C0) * 9];                                                       \
        s_w2[BI][t0] = make_float2(w, w);                                                    \
        if (t1 < 144) {                                                                      \
            float w2v = wgt[wi1 + (C0) * 9];                                                 \
            s_w2[BI][t1] = make_float2(w2v, w2v);                                            \
        }                                                                                    \
    } while (0)

    // ---- prologue: stage step 0 ----
    STAGE_STEP(0, 0);
    __pipeline_commit();
    STAGE_W(0, 0);

    ull acc[4][4];
#pragma unroll
    for (int o = 0; o < 4; o++)
#pragma unroll
        for (int r = 0; r < 4; r++) acc[o][r] = 0ULL;

    int cur = 0;
    for (int s = 0; s < nsteps; s++) {
        int nxt = (cur == 2) ? 0 : cur + 1;
        if (s + 1 < nsteps) {
            const int c0n = (s + 1) * 4;
            STAGE_STEP(nxt, c0n);
            __pipeline_commit();
            STAGE_W(nxt, c0n);
            __pipeline_wait_prior(1);
        } else {
            __pipeline_wait_prior(0);
        }
        __syncthreads();   // single barrier per step

        // ---- compute from buffer cur ----
#pragma unroll
        for (int ck = 0; ck < 4; ck++) {
            ull P[6][3];
#pragma unroll
            for (int iy = 0; iy < 6; iy++) {
                const float* rp = &s_in[cur][ck][ty * 4 + iy][2 + 2 * tx];
                ull a = *(const ull*)rp;
                ull bb = *(const ull*)(rp + 2);
                ull c = *(const ull*)(rp + 4);
                P[iy][0] = midpair(a, bb);
                P[iy][1] = bb;
                P[iy][2] = midpair(bb, c);
            }
#pragma unroll
            for (int o = 0; o < 4; o++) {
                const float2* wrow = &s_w2[cur][o * 36 + ck * 9];
#pragma unroll
                for (int ky = 0; ky < 3; ky++) {
#pragma unroll
                    for (int kx = 0; kx < 3; kx++) {
                        ull w2 = *(const ull*)&wrow[ky * 3 + kx];
#pragma unroll
                        for (int r = 0; r < 4; r++)
                            fma2(acc[o][r], P[r + ky][kx], w2);
                    }
                }
            }
        }
        cur = nxt;
    }

    // ---- epilogue ----
#pragma unroll
    for (int o = 0; o < 4; o++) {
        int oc = oc0 + o;
        float bv = bias[oc];
#pragma unroll
        for (int rr = 0; rr < 4; rr++) {
            int gy = gy0 + ty * 4 + rr;
            int gx = 2 * tx;
            float v0, v1;
            unpack2(acc[o][rr], v0, v1);
            v0 += bv; v1 += bv;
            if (MODE <= 1) {
                v0 = (v0 >= 0.f) ? v0 : 0.1f * v0;
                v1 = (v1 >= 0.f) ? v1 : 0.1f * v1;
                *(float2*)&out[((b * 64 + oc) * HH + gy) * WW + gx] = make_float2(v0, v1);
            } else {
                if (oc < 288) {
                    const float* fl = (oc < 144) ? flow1 : flow2;
                    const float* fr = fl + ((size_t)(b * 2 + (1 - (oc & 1)))) * HW + gy * WW + gx;
                    float2 f = *(const float2*)fr;
                    float2 r = make_float2(10.f * tanhf(v0) + f.x, 10.f * tanhf(v1) + f.y);
                    *(float2*)&out[(size_t)b * 288 * HW + (size_t)oc * HW + gy * WW + gx] = r;
                } else {
                    float2 r = make_float2(1.f / (1.f + expf(-v0)), 1.f / (1.f + expf(-v1)));
                    *(float2*)&out2[(size_t)b * 144 * HW + (size_t)(oc - 288) * HW + gy * WW + gx] = r;
                }
            }
        }
    }
#undef STAGE_STEP
#undef STAGE_W
}

// ---------------- deformable conv ----------------
#define SSTRIDE 1156

__global__ void deform_kernel(
    const float* __restrict__ xt,
    const float* __restrict__ off,
    const float* __restrict__ msk,
    const float* __restrict__ wd,
    const float* __restrict__ bias,
    float* __restrict__ out)
{
    extern __shared__ float s_sm[];   // 16 * SSTRIDE floats
    int b = blockIdx.z;
    int h = blockIdx.y;
    int w0 = blockIdx.x * 16;
    int tid = threadIdx.x;

    // ---------- phase 1: bilinear gather into smem ----------
    {
        int px = tid & 15;
        int ww = w0 + px;
        int pospix = h * WW + ww;
        const float* offb = off + (size_t)b * 288 * HW + pospix;
        const float* mskb = msk + (size_t)b * 144 * HW + pospix;
        const float* xb = xt + (size_t)b * HW * 128;
#pragma unroll 1
        for (int it = 0; it < 9; it++) {
            int gk = (tid >> 4) + it * 16;          // 0..143
            int g = gk / 9, k = gk - g * 9;
            int ky = k / 3, kx = k - ky * 3;
            int oc = g * 18 + k * 2;
            float dy = offb[(size_t)oc * HW];
            float dx = offb[(size_t)(oc + 1) * HW];
            float m = mskb[(size_t)gk * HW];
            float py = dy + (float)(ky + h - 1);
            float pxx = dx + (float)(kx + ww - 1);
            float fy0 = floorf(py), fx0 = floorf(pxx);
            float wy1 = py - fy0, wx1 = pxx - fx0;
            int iy0 = (int)fy0, ix0 = (int)fx0;
            float a[8];
#pragma unroll
            for (int i = 0; i < 8; i++) a[i] = 0.f;
#pragma unroll
            for (int dyc = 0; dyc < 2; dyc++) {
#pragma unroll
                for (int dxc = 0; dxc < 2; dxc++) {
                    int yy = iy0 + dyc, xx = ix0 + dxc;
                    if ((unsigned)yy < HH && (unsigned)xx < WW) {
                        float wc = (dyc ? wy1 : 1.f - wy1) * (dxc ? wx1 : 1.f - wx1);
                        const float4* p = (const float4*)(xb + ((size_t)yy * WW + xx) * 128 + g * 8);
                        float4 v0 = p[0], v1 = p[1];
                        a[0] += wc * v0.x; a[1] += wc * v0.y; a[2] += wc * v0.z; a[3] += wc * v0.w;
                        a[4] += wc * v1.x; a[5] += wc * v1.y; a[6] += wc * v1.z; a[7] += wc * v1.w;
                    }
                }
            }
            float* sp = s_sm + px * SSTRIDE + g * 72 + k * 8;
            ((float4*)sp)[0] = make_float4(a[0] * m, a[1] * m, a[2] * m, a[3] * m);
            ((float4*)sp)[1] = make_float4(a[4] * m, a[5] * m, a[6] * m, a[7] * m);
        }
    }
    __syncthreads();

    // ---------- phase 2: out[16px][64oc] = s @ wd, f32x2 packed ----------
    {
        int og = tid & 15;       // 4 output channels: og*4..og*4+3
        int p2 = tid >> 4;       // pixel 0..15
        const ulonglong2* wdv = (const ulonglong2*)wd;
        const float4* sr4 = (const float4*)(s_sm + p2 * SSTRIDE);
        float4 bb = ((const float4*)bias)[og];
        ull a01 = pack2(bb.x, bb.y);
        ull a23 = pack2(bb.z, bb.w);
#pragma unroll 2
        for (int kk4 = 0; kk4 < 288; kk4++) {
            float4 sv = sr4[kk4];
            {
                ull ss = pack2(sv.x, sv.x);
                ulonglong2 wv = wdv[(kk4 * 4 + 0) * 16 + og];
                fma2(a01, wv.x, ss); fma2(a23, wv.y, ss);
            }
            {
                ull ss = pack2(sv.y, sv.y);
                ulonglong2 wv = wdv[(kk4 * 4 + 1) * 16 + og];
                fma2(a01, wv.x, ss); fma2(a23, wv.y, ss);
            }
            {
                ull ss = pack2(sv.z, sv.z);
                ulonglong2 wv = wdv[(kk4 * 4 + 2) * 16 + og];
                fma2(a01, wv.x, ss); fma2(a23, wv.y, ss);
            }
            {
                ull ss = pack2(sv.w, sv.w);
                ulonglong2 wv = wdv[(kk4 * 4 + 3) * 16 + og];
                fma2(a01, wv.x, ss); fma2(a23, wv.y, ss);
            }
        }
        float r0, r1, r2, r3;
        unpack2(a01, r0, r1);
        unpack2(a23, r2, r3);
        int oc = og * 4;
        size_t ob = (size_t)b * 64 * HW + (size_t)h * WW + w0 + p2;
        out[ob + (size_t)(oc + 0) * HW] = r0;
        out[ob + (size_t)(oc + 1) * HW] = r1;
        out[ob + (size_t)(oc + 2) * HW] = r2;
        out[ob + (size_t)(oc + 3) * HW] = r3;
    }
}

// ---------------- launch ----------------
extern "C" void kernel_launch(void* const* d_in, const int* in_sizes, int n_in,
                              void* d_out, int out_size)
{
    const float* x      = (const float*)d_in[0];
    const float* extra  = (const float*)d_in[1];
    const float* flow1  = (const float*)d_in[2];
    const float* flow2  = (const float*)d_in[3];
    const float* weight = (const float*)d_in[4];
    const float* bias   = (const float*)d_in[5];
    const float* ow0    = (const float*)d_in[6];
    const float* ob0    = (const float*)d_in[7];
    const float* ow1    = (const float*)d_in[8];
    const float* ob1    = (const float*)d_in[9];
    const float* ow2    = (const float*)d_in[10];
    const float* ob2    = (const float*)d_in[11];
    const float* ow3    = (const float*)d_in[12];
    const float* ob3    = (const float*)d_in[13];
    float* out = (float*)d_out;

    void *ph0, *ph1, *poff, *pmask, *pxt, *pwd;
    cudaGetSymbolAddress(&ph0, g_h0);
    cudaGetSymbolAddress(&ph1, g_h1);
    cudaGetSymbolAddress(&poff, g_off);
    cudaGetSymbolAddress(&pmask, g_mask);
    cudaGetSymbolAddress(&pxt, g_xt);
    cudaGetSymbolAddress(&pwd, g_wd);
    float* h0 = (float*)ph0;
    float* h1 = (float*)ph1;
    float* offb = (float*)poff;
    float* maskb = (float*)pmask;
    float* xtb = (float*)pxt;
    float* wdb = (float*)pwd;

    // transpose x -> NHWC
    transpose_x_kernel<<<dim3(12, 96, BATCH), dim3(32, 8)>>>(x, xtb);
    // weight transpose for deform GEMM
    prep_wd_kernel<<<288, 256>>>(weight, wdb);

    // conv chain (96-thread blocks, 12 spatial tiles, 3-deep pipeline)
    conv3x3_kernel<196, 0><<<dim3(12, 16, BATCH), 96>>>(
        nullptr, extra, flow1, flow2, ow0, ob0, h0, nullptr);
    conv3x3_kernel<64, 1><<<dim3(12, 16, BATCH), 96>>>(
        h0, nullptr, nullptr, nullptr, ow1, ob1, h1, nullptr);
    conv3x3_kernel<64, 1><<<dim3(12, 16, BATCH), 96>>>(
        h1, nullptr, nullptr, nullptr, ow2, ob2, h0, nullptr);
    conv3x3_kernel<64, 2><<<dim3(12, 108, BATCH), 96>>>(
        h0, nullptr, flow1, flow2, ow3, ob3, offb, maskb);

    // deformable conv
    int smem = 16 * SSTRIDE * (int)sizeof(float);   // 73984 bytes
    cudaFuncSetAttribute(deform_kernel, cudaFuncAttributeMaxDynamicSharedMemorySize, smem);
    deform_kernel<<<dim3(6, 96, BATCH), 256, smem>>>(xtb, offb, maskb, wdb, bias, out);
}

// round 10
// speedup vs baseline: 1.3749x; 1.0131x over previous
#include <cuda_runtime.h>
#include <cuda_pipeline.h>
#include <math.h>

#define HH 96
#define WW 96
#define HW 9216
#define BATCH 4

typedef unsigned long long ull;

// ---------------- scratch (static device globals; no allocation) ----------------
__device__ float g_h0[BATCH * 64 * HW];
__device__ float g_h1[BATCH * 64 * HW];
__device__ float g_off[BATCH * 288 * HW];
__device__ float g_mask[BATCH * 144 * HW];
__device__ float g_xt[BATCH * HW * 128];   // NHWC transpose of x
__device__ float g_wd[1152 * 64];          // deform weight, [kk][o]

// ---------------- packed f32x2 helpers ----------------
__device__ __forceinline__ void fma2(ull& d, ull a, ull b) {
    asm("fma.rn.f32x2 %0, %1, %2, %0;" : "+l"(d) : "l"(a), "l"(b));
}
__device__ __forceinline__ ull pack2(float lo, float hi) {
    ull r;
    asm("mov.b64 %0, {%1, %2};" : "=l"(r) : "f"(lo), "f"(hi));
    return r;
}
__device__ __forceinline__ void unpack2(ull p, float& lo, float& hi) {
    asm("mov.b64 {%0, %1}, %2;" : "=f"(lo), "=f"(hi) : "l"(p));
}
__device__ __forceinline__ ull midpair(ull a, ull b) {
    return (a >> 32) | (b << 32);   // {hi(a), lo(b)}
}

// ---------------- transpose x: NCHW -> N(HW)C ----------------
__global__ void transpose_x_kernel(const float* __restrict__ x, float* __restrict__ xt) {
    __shared__ float t[32][33];
    int b = blockIdx.z, y = blockIdx.y;
    int c0 = (blockIdx.x & 3) * 32;
    int w0 = (blockIdx.x >> 2) * 32;
    int tx = threadIdx.x, ty = threadIdx.y;
#pragma unroll
    for (int j = 0; j < 4; j++) {
        int c = c0 + ty + j * 8;
        t[ty + j * 8][tx] = x[((b * 128 + c) * HH + y) * WW + w0 + tx];
    }
    __syncthreads();
#pragma unroll
    for (int j = 0; j < 4; j++) {
        int w = w0 + ty + j * 8;
        xt[((size_t)b * HW + (size_t)y * WW + w) * 128 + c0 + tx] = t[tx][ty + j * 8];
    }
}

// ---------------- deform-weight transpose ----------------
__global__ void prep_wd_kernel(const float* __restrict__ wgt, float* __restrict__ wd) {
    int i = blockIdx.x * 256 + threadIdx.x;   // < 73728
    int kk = i >> 6, o = i & 63;
    int g = kk / 72, r = kk - g * 72;
    int k = r >> 3, c = r & 7;
    wd[i] = wgt[(o * 128 + g * 8 + c) * 9 + k];
}

// ---------------- 3x3 SAME conv, 3-deep cp.async pipeline, CK channels/step ----------------
// Tile: 96 cols x 8 rows. Block = 96 threads. Thread: 2 cols, 4 rows, 4 oc.
// smem: interior col g at j = 4+g (16B-aligned cp.async dst); j<4 / j>=100 permanent zeros.
#define SROW 104

template <int CIN, int MODE, int CK>
__global__ __launch_bounds__(96, 5) void conv3x3_kernel(
    const float* __restrict__ in,
    const float* __restrict__ extra,
    const float* __restrict__ flow1,
    const float* __restrict__ flow2,
    const float* __restrict__ wgt,
    const float* __restrict__ bias,
    float* __restrict__ out,
    float* __restrict__ out2)
{
    __shared__ float s_in[3][CK][10][SROW];
    __shared__ float2 s_w2[3][36 * CK];

    const int b = blockIdx.z;
    const int oc0 = blockIdx.y * 4;
    const int gy0 = blockIdx.x * 8;        // 12 tiles of 8 rows
    const int tid = threadIdx.x;           // 0..95
    const int tx = tid % 48;
    const int ty = tid / 48;               // 0..1
    const int nsteps = CIN / CK;
    constexpr int NCOPY = CK * 240 / 96;   // 16B cp.async per thread per step
    constexpr int NW = 36 * CK;            // weight entries per step
    constexpr int NWS = (NW + 95) / 96;    // weight slots per thread

    // ---- pre-zero halo columns (all 3 buffers), once ----
    const float4 z4 = make_float4(0.f, 0.f, 0.f, 0.f);
    for (int i = tid; i < 60 * CK; i += 96) {
        int bi = i / (20 * CK), rem = i % (20 * CK);
        int ckr = rem / 20, rem2 = rem % 20;
        int r = rem2 >> 1, side = rem2 & 1;
        *(float4*)&s_in[bi][ckr][r][side ? 100 : 0] = z4;
    }
    // ---- pre-zero out-of-range rows (all 3 buffers), once ----
    if (gy0 == 0 || gy0 == 88) {
        int rr = (gy0 == 0) ? 0 : 9;
        for (int i = tid; i < 78 * CK; i += 96) {
            int bi = i / (26 * CK), rem = i % (26 * CK);
            int ckr = rem / 26, q = rem % 26;
            ((float4*)&s_in[bi][ckr][rr][0])[q] = z4;
        }
    }

    // ---- precompute staging offsets ----
    int soff[NCOPY], doff[NCOPY];
    unsigned vmask = 0;
#pragma unroll
    for (int i = 0; i < NCOPY; i++) {
        int t = tid + 96 * i;
        int q = t % 24, rc = t / 24;
        int ckr = rc / 10, rr = rc - ckr * 10;
        int gy = gy0 + rr - 1;
        soff[i] = ckr * HW + gy * WW + 4 * q;
        doff[i] = rc * SROW + 4 + 4 * q;
        if ((unsigned)gy < (unsigned)HH) vmask |= 1u << i;
    }

    // ---- precompute weight slot bases ----
    int wbase[NWS];
#pragma unroll
    for (int j = 0; j < NWS; j++) {
        int widx = tid + 96 * j;
        if (widx < NW) {
            int o = widx / (9 * CK), rem = widx % (9 * CK);
            int ckr = rem / 9, k = rem % 9;
            wbase[j] = ((oc0 + o) * CIN + ckr) * 9 + k;
        } else wbase[j] = 0;
    }

#define STAGE_STEP(BI, C0)                                                                   \
    do {                                                                                     \
        float* db = &s_in[BI][0][0][0];                                                      \
        if (MODE != 0 || (C0) < 192) {                                                       \
            const float* base = (MODE == 0)                                                  \
                ? extra + (size_t)(b * 192 + (C0)) * HW                                      \
                : in + (size_t)(b * CIN + (C0)) * HW;                                        \
            _Pragma("unroll")                                                                \
            for (int i = 0; i < NCOPY; i++)                                                  \
                if ((vmask >> i) & 1)                                                        \
                    __pipeline_memcpy_async(db + doff[i], base + soff[i], 16);               \
        } else {                                                                             \
            _Pragma("unroll")                                                                \
            for (int i = 0; i < NCOPY; i++) {                                                \
                if ((vmask >> i) & 1) {                                                      \
                    int t = tid + 96 * i;                                                    \
                    int q = t % 24, rc = t / 24;                                             \
                    int ckr = rc / 10, rr = rc - ckr * 10;                                   \
                    int gy = gy0 + rr - 1;                                                   \
                    const float* src = ((ckr < 2) ? flow1 : flow2)                           \
                                       + (size_t)(b * 2 + (ckr & 1)) * HW;                   \
                    __pipeline_memcpy_async(db + doff[i], src + gy * WW + 4 * q, 16);        \
                }                                                                            \
            }                                                                                \
        }                                                                                    \
    } while (0)

#define STAGE_W(BI, C0)                                                                      \
    do {                                                                                     \
        _Pragma("unroll")                                                                    \
        for (int j = 0; j < NWS; j++) {                                                      \
            int widx = tid + 96 * j;                                                         \
            if (widx < NW) {                                                                 \
                float w = wgt[wbase[j] + (C0) * 9];                                          \
                s_w2[BI][widx] = make_float2(w, w);                                          \
            }                                                                                \
        }                                                                                    \
    } while (0)

    // ---- prologue: stage step 0 ----
    STAGE_STEP(0, 0);
    __pipeline_commit();
    STAGE_W(0, 0);

    ull acc[4][4];
#pragma unroll
    for (int o = 0; o < 4; o++)
#pragma unroll
        for (int r = 0; r < 4; r++) acc[o][r] = 0ULL;

    int cur = 0;
    for (int s = 0; s < nsteps; s++) {
        int nxt = (cur == 2) ? 0 : cur + 1;
        if (s + 1 < nsteps) {
            const int c0n = (s + 1) * CK;
            STAGE_STEP(nxt, c0n);
            __pipeline_commit();
            STAGE_W(nxt, c0n);
            __pipeline_wait_prior(1);
        } else {
            __pipeline_wait_prior(0);
        }
        __syncthreads();   // single barrier per step

        // ---- compute from buffer cur ----
#pragma unroll
        for (int ck = 0; ck < CK; ck++) {
            ull P[6][3];
#pragma unroll
            for (int iy = 0; iy < 6; iy++) {
                const float* rp = &s_in[cur][ck][ty * 4 + iy][2 + 2 * tx];
                ull a = *(const ull*)rp;
                ull bb = *(const ull*)(rp + 2);
                ull c = *(const ull*)(rp + 4);
                P[iy][0] = midpair(a, bb);
                P[iy][1] = bb;
                P[iy][2] = midpair(bb, c);
            }
#pragma unroll
            for (int o = 0; o < 4; o++) {
                const float2* wrow = &s_w2[cur][o * 9 * CK + ck * 9];
#pragma unroll
                for (int ky = 0; ky < 3; ky++) {
#pragma unroll
                    for (int kx = 0; kx < 3; kx++) {
                        ull w2 = *(const ull*)&wrow[ky * 3 + kx];
#pragma unroll
                        for (int r = 0; r < 4; r++)
                            fma2(acc[o][r], P[r + ky][kx], w2);
                    }
                }
            }
        }
        cur = nxt;
    }

    // ---- epilogue ----
#pragma unroll
    for (int o = 0; o < 4; o++) {
        int oc = oc0 + o;
        float bv = bias[oc];
#pragma unroll
        for (int rr = 0; rr < 4; rr++) {
            int gy = gy0 + ty * 4 + rr;
            int gx = 2 * tx;
            float v0, v1;
            unpack2(acc[o][rr], v0, v1);
            v0 += bv; v1 += bv;
            if (MODE <= 1) {
                v0 = (v0 >= 0.f) ? v0 : 0.1f * v0;
                v1 = (v1 >= 0.f) ? v1 : 0.1f * v1;
                *(float2*)&out[((b * 64 + oc) * HH + gy) * WW + gx] = make_float2(v0, v1);
            } else {
                if (oc < 288) {
                    const float* fl = (oc < 144) ? flow1 : flow2;
                    const float* fr = fl + ((size_t)(b * 2 + (1 - (oc & 1)))) * HW + gy * WW + gx;
                    float2 f = *(const float2*)fr;
                    float2 r = make_float2(10.f * tanhf(v0) + f.x, 10.f * tanhf(v1) + f.y);
                    *(float2*)&out[(size_t)b * 288 * HW + (size_t)oc * HW + gy * WW + gx] = r;
                } else {
                    float2 r = make_float2(1.f / (1.f + expf(-v0)), 1.f / (1.f + expf(-v1)));
                    *(float2*)&out2[(size_t)b * 144 * HW + (size_t)(oc - 288) * HW + gy * WW + gx] = r;
                }
            }
        }
    }
#undef STAGE_STEP
#undef STAGE_W
}

// ---------------- deformable conv ----------------
#define SSTRIDE 1156

__global__ void deform_kernel(
    const float* __restrict__ xt,
    const float* __restrict__ off,
    const float* __restrict__ msk,
    const float* __restrict__ wd,
    const float* __restrict__ bias,
    float* __restrict__ out)
{
    extern __shared__ float s_sm[];   // 16 * SSTRIDE floats
    int b = blockIdx.z;
    int h = blockIdx.y;
    int w0 = blockIdx.x * 16;
    int tid = threadIdx.x;

    // ---------- phase 1: bilinear gather into smem ----------
    {
        int px = tid & 15;
        int ww = w0 + px;
        int pospix = h * WW + ww;
        const float* offb = off + (size_t)b * 288 * HW + pospix;
        const float* mskb = msk + (size_t)b * 144 * HW + pospix;
        const float* xb = xt + (size_t)b * HW * 128;
#pragma unroll 1
        for (int it = 0; it < 9; it++) {
            int gk = (tid >> 4) + it * 16;          // 0..143
            int g = gk / 9, k = gk - g * 9;
            int ky = k / 3, kx = k - ky * 3;
            int oc = g * 18 + k * 2;
            float dy = offb[(size_t)oc * HW];
            float dx = offb[(size_t)(oc + 1) * HW];
            float m = mskb[(size_t)gk * HW];
            float py = dy + (float)(ky + h - 1);
            float pxx = dx + (float)(kx + ww - 1);
            float fy0 = floorf(py), fx0 = floorf(pxx);
            float wy1 = py - fy0, wx1 = pxx - fx0;
            int iy0 = (int)fy0, ix0 = (int)fx0;
            float a[8];
#pragma unroll
            for (int i = 0; i < 8; i++) a[i] = 0.f;
#pragma unroll
            for (int dyc = 0; dyc < 2; dyc++) {
#pragma unroll
                for (int dxc = 0; dxc < 2; dxc++) {
                    int yy = iy0 + dyc, xx = ix0 + dxc;
                    if ((unsigned)yy < HH && (unsigned)xx < WW) {
                        float wc = (dyc ? wy1 : 1.f - wy1) * (dxc ? wx1 : 1.f - wx1);
                        const float4* p = (const float4*)(xb + ((size_t)yy * WW + xx) * 128 + g * 8);
                        float4 v0 = p[0], v1 = p[1];
                        a[0] += wc * v0.x; a[1] += wc * v0.y; a[2] += wc * v0.z; a[3] += wc * v0.w;
                        a[4] += wc * v1.x; a[5] += wc * v1.y; a[6] += wc * v1.z; a[7] += wc * v1.w;
                    }
                }
            }
            float* sp = s_sm + px * SSTRIDE + g * 72 + k * 8;
            ((float4*)sp)[0] = make_float4(a[0] * m, a[1] * m, a[2] * m, a[3] * m);
            ((float4*)sp)[1] = make_float4(a[4] * m, a[5] * m, a[6] * m, a[7] * m);
        }
    }
    __syncthreads();

    // ---------- phase 2: out[16px][64oc] = s @ wd, f32x2 packed ----------
    {
        int og = tid & 15;       // 4 output channels: og*4..og*4+3
        int p2 = tid >> 4;       // pixel 0..15
        const ulonglong2* wdv = (const ulonglong2*)wd;
        const float4* sr4 = (const float4*)(s_sm + p2 * SSTRIDE);
        float4 bb = ((const float4*)bias)[og];
        ull a01 = pack2(bb.x, bb.y);
        ull a23 = pack2(bb.z, bb.w);
#pragma unroll 2
        for (int kk4 = 0; kk4 < 288; kk4++) {
            float4 sv = sr4[kk4];
            {
                ull ss = pack2(sv.x, sv.x);
                ulonglong2 wv = wdv[(kk4 * 4 + 0) * 16 + og];
                fma2(a01, wv.x, ss); fma2(a23, wv.y, ss);
            }
            {
                ull ss = pack2(sv.y, sv.y);
                ulonglong2 wv = wdv[(kk4 * 4 + 1) * 16 + og];
                fma2(a01, wv.x, ss); fma2(a23, wv.y, ss);
            }
            {
                ull ss = pack2(sv.z, sv.z);
                ulonglong2 wv = wdv[(kk4 * 4 + 2) * 16 + og];
                fma2(a01, wv.x, ss); fma2(a23, wv.y, ss);
            }
            {
                ull ss = pack2(sv.w, sv.w);
                ulonglong2 wv = wdv[(kk4 * 4 + 3) * 16 + og];
                fma2(a01, wv.x, ss); fma2(a23, wv.y, ss);
            }
        }
        float r0, r1, r2, r3;
        unpack2(a01, r0, r1);
        unpack2(a23, r2, r3);
        int oc = og * 4;
        size_t ob = (size_t)b * 64 * HW + (size_t)h * WW + w0 + p2;
        out[ob + (size_t)(oc + 0) * HW] = r0;
        out[ob + (size_t)(oc + 1) * HW] = r1;
        out[ob + (size_t)(oc + 2) * HW] = r2;
        out[ob + (size_t)(oc + 3) * HW] = r3;
    }
}

// ---------------- launch ----------------
extern "C" void kernel_launch(void* const* d_in, const int* in_sizes, int n_in,
                              void* d_out, int out_size)
{
    const float* x      = (const float*)d_in[0];
    const float* extra  = (const float*)d_in[1];
    const float* flow1  = (const float*)d_in[2];
    const float* flow2  = (const float*)d_in[3];
    const float* weight = (const float*)d_in[4];
    const float* bias   = (const float*)d_in[5];
    const float* ow0    = (const float*)d_in[6];
    const float* ob0    = (const float*)d_in[7];
    const float* ow1    = (const float*)d_in[8];
    const float* ob1    = (const float*)d_in[9];
    const float* ow2    = (const float*)d_in[10];
    const float* ob2    = (const float*)d_in[11];
    const float* ow3    = (const float*)d_in[12];
    const float* ob3    = (const float*)d_in[13];
    float* out = (float*)d_out;

    void *ph0, *ph1, *poff, *pmask, *pxt, *pwd;
    cudaGetSymbolAddress(&ph0, g_h0);
    cudaGetSymbolAddress(&ph1, g_h1);
    cudaGetSymbolAddress(&poff, g_off);
    cudaGetSymbolAddress(&pmask, g_mask);
    cudaGetSymbolAddress(&pxt, g_xt);
    cudaGetSymbolAddress(&pwd, g_wd);
    float* h0 = (float*)ph0;
    float* h1 = (float*)ph1;
    float* offb = (float*)poff;
    float* maskb = (float*)pmask;
    float* xtb = (float*)pxt;
    float* wdb = (float*)pwd;

    // transpose x -> NHWC
    transpose_x_kernel<<<dim3(12, 96, BATCH), dim3(32, 8)>>>(x, xtb);
    // weight transpose for deform GEMM
    prep_wd_kernel<<<288, 256>>>(weight, wdb);

    // conv chain (96-thread blocks, 12 spatial tiles, 3-deep pipeline)
    conv3x3_kernel<196, 0, 4><<<dim3(12, 16, BATCH), 96>>>(
        nullptr, extra, flow1, flow2, ow0, ob0, h0, nullptr);
    conv3x3_kernel<64, 1, 2><<<dim3(12, 16, BATCH), 96>>>(
        h0, nullptr, nullptr, nullptr, ow1, ob1, h1, nullptr);
    conv3x3_kernel<64, 1, 2><<<dim3(12, 16, BATCH), 96>>>(
        h1, nullptr, nullptr, nullptr, ow2, ob2, h0, nullptr);
    conv3x3_kernel<64, 2, 2><<<dim3(12, 108, BATCH), 96>>>(
        h0, nullptr, flow1, flow2, ow3, ob3, offb, maskb);

    // deformable conv
    int smem = 16 * SSTRIDE * (int)sizeof(float);   // 73984 bytes
    cudaFuncSetAttribute(deform_kernel, cudaFuncAttributeMaxDynamicSharedMemorySize, smem);
    deform_kernel<<<dim3(6, 96, BATCH), 256, smem>>>(xtb, offb, maskb, wdb, bias, out);
}